// round 8
// baseline (speedup 1.0000x reference)
#include <cuda_runtime.h>

#define NPTS   16384
#define EPSC   1e-5f
#define L2E    1.44269504088896340736f

#define QP     100    // qkv smem pitch (floats); conflict-free float4
#define T2     64     // K2 tile points
#define H2     80     // K2 halo rows
#define RAD    8

// 25.2MB device scratch: [global_point][96 floats as 24 float4], q/k pre-scaled
__device__ float4 qkv_g[NPTS * 4 * 24];

#define PACK2(dst, lo, hi) asm("mov.b64 %0, {%1, %2};" : "=l"(dst) : "f"(lo), "f"(hi))
#define UNPACK2(lo, hi, v) asm("mov.b64 {%0, %1}, %2;" : "=f"(lo), "=f"(hi) : "l"(v))
#define FMA2(d, a, b, c)   asm("fma.rn.f32x2 %0, %1, %2, %3;" : "=l"(d) : "l"(a), "l"(b), "l"(c))

// ---------------- K1: qkv GEMM (no halo) ----------------
__global__ __launch_bounds__(256, 3)
void k1_qkv(const float* __restrict__ features,
            const float* __restrict__ Wq,  const float* __restrict__ bq,
            const float* __restrict__ Wk,  const float* __restrict__ bk,
            const float* __restrict__ Wv,  const float* __restrict__ bv,
            const float* __restrict__ w1_g, const float* __restrict__ w1_v)
{
    __shared__ float fsh[128*64 + 16];
    float* cS = fsh + 128*64;

    const int tid   = threadIdx.x;
    const int gbase = (blockIdx.x >> 7)*NPTS + (blockIdx.x & 127)*128;

    // stage 128 contiguous feature rows
    {
        const float4* fg = (const float4*)features + (size_t)gbase*16;
        float4* fs4 = (float4*)fsh;
        for (int i = tid; i < 2048; i += 256) fs4[i] = fg[i];
    }
    if (tid < 16) cS[tid] = w1_g[tid] * rsqrtf(w1_v[tid] + EPSC);

    // per-lane weight column, packed f32x2
    const int warp = tid >> 5, lane = tid & 31;
    int cg, p0, p1;
    if (warp < 3)      { cg = 0; p0 = (warp*128)/3;     p1 = ((warp+1)*128)/3; }
    else if (warp < 6) { cg = 1; p0 = ((warp-3)*128)/3; p1 = ((warp-2)*128)/3; }
    else               { cg = 2; p0 = (warp-6)*64;      p1 = p0 + 64; }
    const int c = cg*32 + lane;

    unsigned long long wp[32];
    float bias;
    if (c < 16) {
        bias = bq[c];
        #pragma unroll
        for (int i = 0; i < 32; ++i) PACK2(wp[i], Wq[(2*i)*16 + c], Wq[(2*i+1)*16 + c]);
    } else if (c < 32) {
        int cc = c - 16; bias = bk[cc];
        #pragma unroll
        for (int i = 0; i < 32; ++i) PACK2(wp[i], Wk[(2*i)*16 + cc], Wk[(2*i+1)*16 + cc]);
    } else {
        int cc = c - 32; bias = bv[cc];
        #pragma unroll
        for (int i = 0; i < 32; ++i) PACK2(wp[i], Wv[(2*i)*64 + cc], Wv[(2*i+1)*64 + cc]);
    }
    __syncthreads();

    const float chan_scale = (c < 32) ? cS[c & 15] : 1.0f;
    float* qf = (float*)qkv_g;

    #pragma unroll 2
    for (int p = p0; p < p1; ++p) {
        const ulonglong2* fr = (const ulonglong2*)(fsh + (p << 6));
        unsigned long long aA = 0ull, aB = 0ull, aC = 0ull, aD = 0ull;
        #pragma unroll
        for (int k2 = 0; k2 < 8; ++k2) {
            ulonglong2 f0 = fr[2*k2];
            ulonglong2 f1 = fr[2*k2 + 1];
            FMA2(aA, f0.x, wp[4*k2    ], aA);
            FMA2(aB, f0.y, wp[4*k2 + 1], aB);
            FMA2(aC, f1.x, wp[4*k2 + 2], aC);
            FMA2(aD, f1.y, wp[4*k2 + 3], aD);
        }
        float x0,x1,x2,x3,x4,x5,x6,x7;
        UNPACK2(x0,x1,aA); UNPACK2(x2,x3,aB); UNPACK2(x4,x5,aC); UNPACK2(x6,x7,aD);
        float s = ((x0+x1)+(x2+x3)) + ((x4+x5)+(x6+x7)) + bias;
        qf[(size_t)(gbase + p)*96 + c] = s * chan_scale;
    }
}

// ---------------- K2: ring attention, 4 threads/point ----------------
// smem floats: qkv 80*100=8000 | scratch 6208 | pts 160 | cst 396
#define K2_SMEM_FLOATS (8000 + 6208 + 160 + 396)

__global__ __launch_bounds__(256, 3)
void k2_attn(const float* __restrict__ points,
             const float* __restrict__ Wp1,
             const float* __restrict__ p_g, const float* __restrict__ p_b,
             const float* __restrict__ p_m, const float* __restrict__ p_v,
             const float* __restrict__ Wp2, const float* __restrict__ bp2,
             const float* __restrict__ w1_g, const float* __restrict__ w1_b,
             const float* __restrict__ w1_m, const float* __restrict__ w1_v,
             const float* __restrict__ Ww1,
             const float* __restrict__ w2_g, const float* __restrict__ w2_b,
             const float* __restrict__ w2_m, const float* __restrict__ w2_v,
             const float* __restrict__ Ww2,  const float* __restrict__ bw2,
             float* __restrict__ out)
{
    extern __shared__ float sm[];
    float* qkv_sh  = sm;                  // 8000
    float* scratch = sm + 8000;           // 6208: e-pairs / S-exchange / out staging
    float* pts_sh  = sm + 8000 + 6208;    // 160
    float* cst     = pts_sh + 160;        // 396
    float2* cM2  = (float2*)(cst);        // 16: (As*s, Bs*s)
    float2* cW2  = (float2*)(cst + 32);   // 16: (Ww1a, Ww1b)
    float*  cP0  = cst + 64;              // 16
    float4* cE4  = (float4*)(cst + 96);   // 8 (log2e-folded)
    float4* cR4  = (float4*)(cst + 128);  // 64 -> occupies cst[128:384)
    float*  misc = cst + 384;             // 12 (NO overlap with cR4)

    const int tid    = threadIdx.x;
    const int bidx   = blockIdx.x;
    const int batch  = bidx >> 8;          // 256 tiles per batch
    const int tstart = (bidx & 255) * T2;

    // ---- stage qkv halo rows from global scratch + coords ----
    {
        for (int i = tid; i < H2*24; i += 256) {
            int h = i / 24, c4 = i % 24;
            int gp = batch*NPTS + ((tstart + h - RAD) & (NPTS - 1));
            float4 v = qkv_g[(size_t)gp*24 + c4];
            *(float4*)(qkv_sh + h*QP + c4*4) = v;
        }
        const float2* pglob = (const float2*)points;
        for (int i = tid; i < H2; i += 256) {
            int gp = batch*NPTS + ((tstart + i - RAD) & (NPTS - 1));
            ((float2*)pts_sh)[i] = pglob[gp];
        }
    }

    // ---- folded constants ----
    if (tid < 64)
        cR4[tid] = make_float4(Wp2[tid], Wp2[64 + tid], bp2[tid], 0.f);
    if (tid < 16) {
        float As  = Wp2[tid]    + Wp2[16+tid] + Wp2[32+tid] + Wp2[48+tid];
        float Bs  = Wp2[64+tid] + Wp2[80+tid] + Wp2[96+tid] + Wp2[112+tid];
        float bps = bp2[tid] + bp2[16+tid] + bp2[32+tid] + bp2[48+tid];
        float s   = w1_g[tid] * rsqrtf(w1_v[tid] + EPSC);
        float w1beff = w1_b[tid] - w1_m[tid]*s;
        cM2[tid] = make_float2(As*s, Bs*s);
        cW2[tid] = make_float2(Ww1[2*tid], Ww1[2*tid+1]);
        cP0[tid] = bps*s + w1beff;
    }
    if (tid < 8) cE4[tid] = make_float4(Ww2[tid]*L2E, Ww2[8+tid]*L2E, bw2[tid]*L2E, 0.f);
    if (tid >= 32 && tid < 34) {
        int t = tid - 32;
        float s = p_g[t] * rsqrtf(p_v[t] + EPSC);
        misc[4+t] = s; misc[6+t] = p_b[t] - p_m[t]*s;
        float s2 = w2_g[t] * rsqrtf(w2_v[t] + EPSC);
        misc[8+t] = s2; misc[10+t] = w2_b[t] - w2_m[t]*s2;
    }
    if (tid >= 36 && tid < 40) misc[tid - 36] = Wp1[tid - 36];
    __syncthreads();

    const int p    = tid & 63;     // point within tile
    const int part = tid >> 6;     // 0..3: j-subset in 2a; 16-channel group in 2b
    const int hme  = p + RAD;

    unsigned long long vacc2[8];
    #pragma unroll
    for (int i = 0; i < 8; ++i) vacc2[i] = 0ull;
    float S0[8], S1[8], SE[8];
    #pragma unroll
    for (int i = 0; i < 8; ++i) { S0[i] = 0.f; S1[i] = 0.f; SE[i] = 0.f; }

    const float W00 = misc[0], W01 = misc[1], W10 = misc[2], W11 = misc[3];
    const float ps0 = misc[4], ps1 = misc[5], pb0 = misc[6], pb1 = misc[7];
    const float w2s0 = misc[8], w2s1 = misc[9], w2b0 = misc[10], w2b1 = misc[11];

    #pragma unroll 1
    for (int chunk = 0; chunk < 2; ++chunk) {
        // ---- 2a: MLP + softmax once per (p, j); this thread: j = chunk*8 + 4k + part
        {
            const float2 pme = ((const float2*)pts_sh)[hme];
            float P[16];
            {
                const float4* q4 = (const float4*)(qkv_sh + hme*QP);
                #pragma unroll
                for (int m4 = 0; m4 < 4; ++m4) {
                    float4 t = q4[m4];
                    P[4*m4  ] = cP0[4*m4  ] - t.x;
                    P[4*m4+1] = cP0[4*m4+1] - t.y;
                    P[4*m4+2] = cP0[4*m4+2] - t.z;
                    P[4*m4+3] = cP0[4*m4+3] - t.w;
                }
            }
            #pragma unroll 1
            for (int k = 0; k < 2; ++k) {
                const int jj  = chunk*8 + k*4 + part;
                const int off = jj - 8 + (jj >> 3);
                const int h   = hme + off;

                const float2 pn = ((const float2*)pts_sh)[h];
                const float dx = pn.x - pme.x;
                const float dy = pn.y - pme.y;
                const float h0 = fmaxf(fmaf(dx*W00 + dy*W10, ps0, pb0), 0.f);
                const float h1 = fmaxf(fmaf(dx*W01 + dy*W11, ps1, pb1), 0.f);

                float t0a = 0.f, t0b = 0.f, t1a = 0.f, t1b = 0.f;
                const float4* k4p = (const float4*)(qkv_sh + h*QP + 16);
                const float4* m4p = (const float4*)cM2;
                const float4* w4p = (const float4*)cW2;
                #pragma unroll
                for (int m4 = 0; m4 < 4; ++m4) {
                    float4 kk = k4p[m4];
                    float4 ma = m4p[2*m4], mb = m4p[2*m4+1];
                    float4 wa = w4p[2*m4], wb = w4p[2*m4+1];
                    int m0 = 4*m4;
                    float wr0 = fmaxf(fmaf(h0, ma.x, fmaf(h1, ma.y, kk.x + P[m0  ])), 0.f);
                    float wr1 = fmaxf(fmaf(h0, ma.z, fmaf(h1, ma.w, kk.y + P[m0+1])), 0.f);
                    float wr2 = fmaxf(fmaf(h0, mb.x, fmaf(h1, mb.y, kk.z + P[m0+2])), 0.f);
                    float wr3 = fmaxf(fmaf(h0, mb.z, fmaf(h1, mb.w, kk.w + P[m0+3])), 0.f);
                    t0a = fmaf(wr0, wa.x, t0a);  t1a = fmaf(wr0, wa.y, t1a);
                    t0b = fmaf(wr1, wa.z, t0b);  t1b = fmaf(wr1, wa.w, t1b);
                    t0a = fmaf(wr2, wb.x, t0a);  t1a = fmaf(wr2, wb.y, t1a);
                    t0b = fmaf(wr3, wb.z, t0b);  t1b = fmaf(wr3, wb.w, t1b);
                }
                float t0 = t0a + t0b, t1 = t1a + t1b;
                t0 = fmaxf(fmaf(t0, w2s0, w2b0), 0.f);
                t1 = fmaxf(fmaf(t1, w2s1, w2b1), 0.f);

                float e[8];
                #pragma unroll
                for (int cc = 0; cc < 8; ++cc) {
                    float4 ce = cE4[cc];
                    e[cc] = fmaf(t0, ce.x, fmaf(t1, ce.y, ce.z));   // log2-domain
                }
                float mx = fmaxf(fmaxf(fmaxf(e[0],e[1]), fmaxf(e[2],e[3])),
                                 fmaxf(fmaxf(e[4],e[5]), fmaxf(e[6],e[7])));
                #pragma unroll
                for (int cc = 0; cc < 8; ++cc) e[cc] = exp2f(e[cc] - mx);
                float sA = (e[0]+e[1]) + (e[2]+e[3]);
                float sB = (e[4]+e[5]) + (e[6]+e[7]);
                const float inv = __fdividef(1.0f, sA + sB);
                #pragma unroll
                for (int cc = 0; cc < 8; ++cc) e[cc] *= inv;

                #pragma unroll
                for (int cc = 0; cc < 8; ++cc) {
                    S0[cc] = fmaf(h0, e[cc], S0[cc]);
                    S1[cc] = fmaf(h1, e[cc], S1[cc]);
                    SE[cc] += e[cc];
                }
                // store e pairs: u64 scratch[cpair*512 + jr*64 + p]
                {
                    float2* ep = (float2*)scratch + (jj & 7)*64 + p;
                    ep[0]    = make_float2(e[0], e[1]);
                    ep[512]  = make_float2(e[2], e[3]);
                    ep[1024] = make_float2(e[4], e[5]);
                    ep[1536] = make_float2(e[6], e[7]);
                }
            }
        }
        __syncthreads();

        // ---- 2b: packed f32x2 weighted-v accumulation (16 channels/thread) ----
        #pragma unroll 2
        for (int jr = 0; jr < 8; ++jr) {
            const int jj  = chunk*8 + jr;
            const int off = jj - 8 + (jj >> 3);
            const int h   = hme + off;
            const unsigned long long* ep = (const unsigned long long*)scratch + jr*64 + p;
            unsigned long long e2[4];
            e2[0] = ep[0]; e2[1] = ep[512]; e2[2] = ep[1024]; e2[3] = ep[1536];
            const ulonglong2* v2 = (const ulonglong2*)(qkv_sh + h*QP + 32 + part*16);
            #pragma unroll
            for (int i = 0; i < 4; ++i) {
                ulonglong2 v = v2[i];
                FMA2(vacc2[2*i  ], v.x, e2[(2*i  ) & 3], vacc2[2*i  ]);
                FMA2(vacc2[2*i+1], v.y, e2[(2*i+1) & 3], vacc2[2*i+1]);
            }
        }
        __syncthreads();
    }

    // ---- unpack accumulators ----
    float va[16];
    #pragma unroll
    for (int t = 0; t < 8; ++t) UNPACK2(va[2*t], va[2*t+1], vacc2[t]);

    // ---- combine S partials across the 4 j-subset threads of this point ----
    {
        float* sp = scratch + p*97 + part*24;
        #pragma unroll
        for (int i = 0; i < 8; ++i) { sp[i] = S0[i]; sp[8+i] = S1[i]; sp[16+i] = SE[i]; }
    }
    __syncthreads();
    #pragma unroll
    for (int q = 1; q < 4; ++q) {
        const float* so = scratch + p*97 + ((part + q) & 3)*24;
        #pragma unroll
        for (int i = 0; i < 8; ++i) { S0[i] += so[i]; S1[i] += so[8+i]; SE[i] += so[16+i]; }
    }
    // apply factored positional term for this thread's 16 channels
    #pragma unroll
    for (int i4 = 0; i4 < 4; ++i4) {
        int cb = part*16 + 4*i4;
        float4 r0 = cR4[cb], r1 = cR4[cb+1], r2 = cR4[cb+2], r3 = cR4[cb+3];
        va[4*i4  ] += fmaf(r0.x, S0[(cb  )&7], fmaf(r0.y, S1[(cb  )&7], r0.z*SE[(cb  )&7]));
        va[4*i4+1] += fmaf(r1.x, S0[(cb+1)&7], fmaf(r1.y, S1[(cb+1)&7], r1.z*SE[(cb+1)&7]));
        va[4*i4+2] += fmaf(r2.x, S0[(cb+2)&7], fmaf(r2.y, S1[(cb+2)&7], r2.z*SE[(cb+2)&7]));
        va[4*i4+3] += fmaf(r3.x, S0[(cb+3)&7], fmaf(r3.y, S1[(cb+3)&7], r3.z*SE[(cb+3)&7]));
    }
    __syncthreads();   // S-exchange reads done before staging overwrite

    // ---- stage (pitch 68) and coalesced write-out ----
    {
        float4* st = (float4*)(scratch + p*68 + part*16);
        #pragma unroll
        for (int i4 = 0; i4 < 4; ++i4)
            st[i4] = make_float4(va[4*i4], va[4*i4+1], va[4*i4+2], va[4*i4+3]);
    }
    __syncthreads();
    {
        float4* dst = (float4*)(out + (size_t)(batch*NPTS + tstart) * 64);
        for (int i = tid; i < T2*16; i += 256) {
            int pp = i >> 4, k4 = i & 15;
            dst[i] = ((const float4*)(scratch + pp*68))[k4];
        }
    }
}

extern "C" void kernel_launch(void* const* d_in, const int* in_sizes, int n_in,
                              void* d_out, int out_size)
{
    const float* points = (const float*)d_in[0];
    const float* feats  = (const float*)d_in[1];
    const float* Wq   = (const float*)d_in[2];
    const float* bq   = (const float*)d_in[3];
    const float* Wk   = (const float*)d_in[4];
    const float* bk   = (const float*)d_in[5];
    const float* Wv   = (const float*)d_in[6];
    const float* bv   = (const float*)d_in[7];
    const float* Wp1  = (const float*)d_in[8];
    const float* p_g  = (const float*)d_in[9];
    const float* p_b  = (const float*)d_in[10];
    const float* p_m  = (const float*)d_in[11];
    const float* p_v  = (const float*)d_in[12];
    const float* Wp2  = (const float*)d_in[13];
    const float* bp2  = (const float*)d_in[14];
    const float* w1_g = (const float*)d_in[15];
    const float* w1_b = (const float*)d_in[16];
    const float* w1_m = (const float*)d_in[17];
    const float* w1_v = (const float*)d_in[18];
    const float* Ww1  = (const float*)d_in[19];
    const float* w2_g = (const float*)d_in[20];
    const float* w2_b = (const float*)d_in[21];
    const float* w2_m = (const float*)d_in[22];
    const float* w2_v = (const float*)d_in[23];
    const float* Ww2  = (const float*)d_in[24];
    const float* bw2  = (const float*)d_in[25];
    float* out = (float*)d_out;

    k1_qkv<<<512, 256>>>(feats, Wq, bq, Wk, bk, Wv, bv, w1_g, w1_v);

    const int smem2 = K2_SMEM_FLOATS * (int)sizeof(float);   // ~59 KB
    cudaFuncSetAttribute(k2_attn,
                         cudaFuncAttributeMaxDynamicSharedMemorySize, smem2);
    k2_attn<<<1024, 256, smem2>>>(points, Wp1,
                                  p_g, p_b, p_m, p_v, Wp2, bp2,
                                  w1_g, w1_b, w1_m, w1_v, Ww1,
                                  w2_g, w2_b, w2_m, w2_v, Ww2, bw2, out);
}

// round 10
// speedup vs baseline: 1.0822x; 1.0822x over previous
#include <cuda_runtime.h>

#define NPTS   16384
#define EPSC   1e-5f
#define L2E    1.44269504088896340736f

#define T2     64            // tile points
#define H2     80            // halo rows
#define RAD    8
#define QP     100           // qkv smem pitch (>=96!); 100 mod 8 == 4 -> conflict-free LDS.128

// smem floats: feat 5120 (reused: e-pairs 4096 / out staging 4352)
//              qkv  80*100=8000 (reused: S-exchange 6208)
//              pts  160 | cst 396
#define SMEM_FLOATS (5120 + 8000 + 160 + 396)

#define PACK2(dst, lo, hi) asm("mov.b64 %0, {%1, %2};" : "=l"(dst) : "f"(lo), "f"(hi))
#define UNPACK2(lo, hi, v) asm("mov.b64 {%0, %1}, %2;" : "=f"(lo), "=f"(hi) : "l"(v))
#define FMA2(d, a, b, c)   asm("fma.rn.f32x2 %0, %1, %2, %3;" : "=l"(d) : "l"(a), "l"(b), "l"(c))

__global__ __launch_bounds__(256, 3)
void pt_fused64(const float* __restrict__ points,
                const float* __restrict__ features,
                const float* __restrict__ Wq,  const float* __restrict__ bq,
                const float* __restrict__ Wk,  const float* __restrict__ bk,
                const float* __restrict__ Wv,  const float* __restrict__ bv,
                const float* __restrict__ Wp1,
                const float* __restrict__ p_g, const float* __restrict__ p_b,
                const float* __restrict__ p_m, const float* __restrict__ p_v,
                const float* __restrict__ Wp2, const float* __restrict__ bp2,
                const float* __restrict__ w1_g, const float* __restrict__ w1_b,
                const float* __restrict__ w1_m, const float* __restrict__ w1_v,
                const float* __restrict__ Ww1,
                const float* __restrict__ w2_g, const float* __restrict__ w2_b,
                const float* __restrict__ w2_m, const float* __restrict__ w2_v,
                const float* __restrict__ Ww2,  const float* __restrict__ bw2,
                float* __restrict__ out)
{
    extern __shared__ float sm[];
    float* feat_sh = sm;                    // 5120 (features -> e-pairs -> staging)
    float* qkv_sh  = sm + 5120;             // 8000 (qkv -> S-exchange)
    float* pts_sh  = sm + 5120 + 8000;      // 160
    float* cst     = pts_sh + 160;          // 396
    float2* cM2  = (float2*)(cst);          // 16: (As*s, Bs*s)
    float2* cW2  = (float2*)(cst + 32);     // 16: (Ww1a, Ww1b)
    float*  cP0  = cst + 64;                // 16
    float*  cS   = cst + 80;                // 16: s
    float4* cE4  = (float4*)(cst + 96);     // 8 (log2e-folded)
    float4* cR4  = (float4*)(cst + 128);    // 64 -> cst[128:384)
    float*  misc = cst + 384;               // 12

    const int tid    = threadIdx.x;
    const int bidx   = blockIdx.x;
    const int batch  = bidx >> 8;            // 256 tiles per batch
    const int tstart = (bidx & 255) * T2;

    // ---- stage halo features + coords ----
    {
        const float4* fglob = (const float4*)features;
        for (int i = tid; i < H2*16; i += 256) {
            int h = i >> 4, k4 = i & 15;
            int gp = batch*NPTS + ((tstart + h - RAD) & (NPTS - 1));
            ((float4*)feat_sh)[h*16 + k4] = fglob[gp*16 + k4];
        }
        const float2* pglob = (const float2*)points;
        for (int i = tid; i < H2; i += 256) {
            int gp = batch*NPTS + ((tstart + i - RAD) & (NPTS - 1));
            ((float2*)pts_sh)[i] = pglob[gp];
        }
    }

    // ---- folded constants ----
    if (tid < 64)
        cR4[tid] = make_float4(Wp2[tid], Wp2[64 + tid], bp2[tid], 0.f);
    if (tid < 16) {
        float As  = Wp2[tid]    + Wp2[16+tid] + Wp2[32+tid] + Wp2[48+tid];
        float Bs  = Wp2[64+tid] + Wp2[80+tid] + Wp2[96+tid] + Wp2[112+tid];
        float bps = bp2[tid] + bp2[16+tid] + bp2[32+tid] + bp2[48+tid];
        float s   = w1_g[tid] * rsqrtf(w1_v[tid] + EPSC);
        float w1beff = w1_b[tid] - w1_m[tid]*s;
        cM2[tid] = make_float2(As*s, Bs*s);
        cW2[tid] = make_float2(Ww1[2*tid], Ww1[2*tid+1]);
        cP0[tid] = bps*s + w1beff;
        cS[tid]  = s;
    }
    if (tid < 8) cE4[tid] = make_float4(Ww2[tid]*L2E, Ww2[8+tid]*L2E, bw2[tid]*L2E, 0.f);
    if (tid >= 32 && tid < 34) {
        int t = tid - 32;
        float s = p_g[t] * rsqrtf(p_v[t] + EPSC);
        misc[4+t] = s; misc[6+t] = p_b[t] - p_m[t]*s;
        float s2 = w2_g[t] * rsqrtf(w2_v[t] + EPSC);
        misc[8+t] = s2; misc[10+t] = w2_b[t] - w2_m[t]*s2;
    }
    if (tid >= 36 && tid < 40) misc[tid - 36] = Wp1[tid - 36];

    // ---- phase-1 weight preload (per-lane channel column, packed f32x2) ----
    const int warp = tid >> 5, lane = tid & 31;
    int cg, p0, p1;
    if (warp < 3)      { cg = 0; p0 = (warp*H2)/3;     p1 = ((warp+1)*H2)/3; }
    else if (warp < 6) { cg = 1; p0 = ((warp-3)*H2)/3; p1 = ((warp-2)*H2)/3; }
    else               { cg = 2; p0 = (warp-6)*40;     p1 = p0 + 40; }
    const int c = cg*32 + lane;

    unsigned long long wp[32];
    float bias;
    if (c < 16) {
        bias = bq[c];
        #pragma unroll
        for (int i = 0; i < 32; ++i) PACK2(wp[i], Wq[(2*i)*16 + c], Wq[(2*i+1)*16 + c]);
    } else if (c < 32) {
        int cc = c - 16; bias = bk[cc];
        #pragma unroll
        for (int i = 0; i < 32; ++i) PACK2(wp[i], Wk[(2*i)*16 + cc], Wk[(2*i+1)*16 + cc]);
    } else {
        int cc = c - 32; bias = bv[cc];
        #pragma unroll
        for (int i = 0; i < 32; ++i) PACK2(wp[i], Wv[(2*i)*64 + cc], Wv[(2*i+1)*64 + cc]);
    }
    __syncthreads();

    const float chan_scale = (c < 32) ? cS[c & 15] : 1.0f;

    // ---- phase 1: q/k/v GEMM over halo rows -> qkv_sh[p*QP + c] ----
    #pragma unroll 2
    for (int p = p0; p < p1; ++p) {
        const ulonglong2* fr = (const ulonglong2*)(feat_sh + (p << 6));
        unsigned long long aA = 0ull, aB = 0ull, aC = 0ull, aD = 0ull;
        #pragma unroll
        for (int k2 = 0; k2 < 8; ++k2) {
            ulonglong2 f0 = fr[2*k2];
            ulonglong2 f1 = fr[2*k2 + 1];
            FMA2(aA, f0.x, wp[4*k2    ], aA);
            FMA2(aB, f0.y, wp[4*k2 + 1], aB);
            FMA2(aC, f1.x, wp[4*k2 + 2], aC);
            FMA2(aD, f1.y, wp[4*k2 + 3], aD);
        }
        float x0,x1,x2,x3,x4,x5,x6,x7;
        UNPACK2(x0,x1,aA); UNPACK2(x2,x3,aB); UNPACK2(x4,x5,aC); UNPACK2(x6,x7,aD);
        float s = ((x0+x1)+(x2+x3)) + ((x4+x5)+(x6+x7)) + bias;
        qkv_sh[p*QP + c] = s * chan_scale;
    }
    __syncthreads();

    // ---- phase 2: attention, 4 threads/point ----
    const int p    = tid & 63;
    const int part = tid >> 6;     // 0..3: j-subset in 2a; 16-channel group in 2b
    const int hme  = p + RAD;

    unsigned long long vacc2[8];
    #pragma unroll
    for (int i = 0; i < 8; ++i) vacc2[i] = 0ull;
    float S0[8], S1[8], SE[8];
    #pragma unroll
    for (int i = 0; i < 8; ++i) { S0[i] = 0.f; S1[i] = 0.f; SE[i] = 0.f; }

    const float W00 = misc[0], W01 = misc[1], W10 = misc[2], W11 = misc[3];
    const float ps0 = misc[4], ps1 = misc[5], pb0 = misc[6], pb1 = misc[7];
    const float w2s0 = misc[8], w2s1 = misc[9], w2b0 = misc[10], w2b1 = misc[11];

    #pragma unroll 1
    for (int chunk = 0; chunk < 2; ++chunk) {
        // ---- 2a: MLP + softmax once per (p, j); this thread: j = chunk*8 + 4k + part
        {
            const float2 pme = ((const float2*)pts_sh)[hme];
            float P[16];
            {
                const float4* q4 = (const float4*)(qkv_sh + hme*QP);
                #pragma unroll
                for (int m4 = 0; m4 < 4; ++m4) {
                    float4 t = q4[m4];
                    P[4*m4  ] = cP0[4*m4  ] - t.x;
                    P[4*m4+1] = cP0[4*m4+1] - t.y;
                    P[4*m4+2] = cP0[4*m4+2] - t.z;
                    P[4*m4+3] = cP0[4*m4+3] - t.w;
                }
            }
            #pragma unroll 1
            for (int k = 0; k < 2; ++k) {
                const int jj  = chunk*8 + k*4 + part;
                const int off = jj - 8 + (jj >> 3);
                const int h   = hme + off;

                const float2 pn = ((const float2*)pts_sh)[h];
                const float dx = pn.x - pme.x;
                const float dy = pn.y - pme.y;
                const float h0 = fmaxf(fmaf(dx*W00 + dy*W10, ps0, pb0), 0.f);
                const float h1 = fmaxf(fmaf(dx*W01 + dy*W11, ps1, pb1), 0.f);

                float t0a = 0.f, t0b = 0.f, t1a = 0.f, t1b = 0.f;
                const float4* k4p = (const float4*)(qkv_sh + h*QP + 16);
                const float4* m4p = (const float4*)cM2;
                const float4* w4p = (const float4*)cW2;
                #pragma unroll
                for (int m4 = 0; m4 < 4; ++m4) {
                    float4 kk = k4p[m4];
                    float4 ma = m4p[2*m4], mb = m4p[2*m4+1];
                    float4 wa = w4p[2*m4], wb = w4p[2*m4+1];
                    int m0 = 4*m4;
                    float wr0 = fmaxf(fmaf(h0, ma.x, fmaf(h1, ma.y, kk.x + P[m0  ])), 0.f);
                    float wr1 = fmaxf(fmaf(h0, ma.z, fmaf(h1, ma.w, kk.y + P[m0+1])), 0.f);
                    float wr2 = fmaxf(fmaf(h0, mb.x, fmaf(h1, mb.y, kk.z + P[m0+2])), 0.f);
                    float wr3 = fmaxf(fmaf(h0, mb.z, fmaf(h1, mb.w, kk.w + P[m0+3])), 0.f);
                    t0a = fmaf(wr0, wa.x, t0a);  t1a = fmaf(wr0, wa.y, t1a);
                    t0b = fmaf(wr1, wa.z, t0b);  t1b = fmaf(wr1, wa.w, t1b);
                    t0a = fmaf(wr2, wb.x, t0a);  t1a = fmaf(wr2, wb.y, t1a);
                    t0b = fmaf(wr3, wb.z, t0b);  t1b = fmaf(wr3, wb.w, t1b);
                }
                float t0 = t0a + t0b, t1 = t1a + t1b;
                t0 = fmaxf(fmaf(t0, w2s0, w2b0), 0.f);
                t1 = fmaxf(fmaf(t1, w2s1, w2b1), 0.f);

                float e[8];
                #pragma unroll
                for (int cc = 0; cc < 8; ++cc) {
                    float4 ce = cE4[cc];
                    e[cc] = fmaf(t0, ce.x, fmaf(t1, ce.y, ce.z));   // log2-domain
                }
                float mx = fmaxf(fmaxf(fmaxf(e[0],e[1]), fmaxf(e[2],e[3])),
                                 fmaxf(fmaxf(e[4],e[5]), fmaxf(e[6],e[7])));
                #pragma unroll
                for (int cc = 0; cc < 8; ++cc) e[cc] = exp2f(e[cc] - mx);
                float sA = (e[0]+e[1]) + (e[2]+e[3]);
                float sB = (e[4]+e[5]) + (e[6]+e[7]);
                const float inv = __fdividef(1.0f, sA + sB);
                #pragma unroll
                for (int cc = 0; cc < 8; ++cc) e[cc] *= inv;

                #pragma unroll
                for (int cc = 0; cc < 8; ++cc) {
                    S0[cc] = fmaf(h0, e[cc], S0[cc]);
                    S1[cc] = fmaf(h1, e[cc], S1[cc]);
                    SE[cc] += e[cc];
                }
                // store e pairs into dead feature buffer: u64 [cpair*512 + jr*64 + p]
                {
                    float2* ep = (float2*)feat_sh + (jj & 7)*64 + p;
                    ep[0]    = make_float2(e[0], e[1]);
                    ep[512]  = make_float2(e[2], e[3]);
                    ep[1024] = make_float2(e[4], e[5]);
                    ep[1536] = make_float2(e[6], e[7]);
                }
            }
        }
        __syncthreads();

        // ---- 2b: packed f32x2 weighted-v accumulation (16 channels/thread) ----
        #pragma unroll 2
        for (int jr = 0; jr < 8; ++jr) {
            const int jj  = chunk*8 + jr;
            const int off = jj - 8 + (jj >> 3);
            const int h   = hme + off;
            const unsigned long long* ep = (const unsigned long long*)feat_sh + jr*64 + p;
            unsigned long long e2[4];
            e2[0] = ep[0]; e2[1] = ep[512]; e2[2] = ep[1024]; e2[3] = ep[1536];
            const ulonglong2* v2 = (const ulonglong2*)(qkv_sh + h*QP + 32 + part*16);
            #pragma unroll
            for (int i = 0; i < 4; ++i) {
                ulonglong2 v = v2[i];
                FMA2(vacc2[2*i  ], v.x, e2[(2*i  ) & 3], vacc2[2*i  ]);
                FMA2(vacc2[2*i+1], v.y, e2[(2*i+1) & 3], vacc2[2*i+1]);
            }
        }
        __syncthreads();
    }

    // ---- unpack accumulators ----
    float va[16];
    #pragma unroll
    for (int t = 0; t < 8; ++t) UNPACK2(va[2*t], va[2*t+1], vacc2[t]);

    // ---- combine S partials across the 4 j-subset threads (qkv_sh now dead) ----
    {
        float* sp = qkv_sh + p*97 + part*24;
        #pragma unroll
        for (int i = 0; i < 8; ++i) { sp[i] = S0[i]; sp[8+i] = S1[i]; sp[16+i] = SE[i]; }
    }
    __syncthreads();
    #pragma unroll
    for (int q = 1; q < 4; ++q) {
        const float* so = qkv_sh + p*97 + ((part + q) & 3)*24;
        #pragma unroll
        for (int i = 0; i < 8; ++i) { S0[i] += so[i]; S1[i] += so[8+i]; SE[i] += so[16+i]; }
    }
    // apply factored positional term for this thread's 16 channels
    #pragma unroll
    for (int i4 = 0; i4 < 4; ++i4) {
        int cb = part*16 + 4*i4;
        float4 r0 = cR4[cb], r1 = cR4[cb+1], r2 = cR4[cb+2], r3 = cR4[cb+3];
        va[4*i4  ] += fmaf(r0.x, S0[(cb  )&7], fmaf(r0.y, S1[(cb  )&7], r0.z*SE[(cb  )&7]));
        va[4*i4+1] += fmaf(r1.x, S0[(cb+1)&7], fmaf(r1.y, S1[(cb+1)&7], r1.z*SE[(cb+1)&7]));
        va[4*i4+2] += fmaf(r2.x, S0[(cb+2)&7], fmaf(r2.y, S1[(cb+2)&7], r2.z*SE[(cb+2)&7]));
        va[4*i4+3] += fmaf(r3.x, S0[(cb+3)&7], fmaf(r3.y, S1[(cb+3)&7], r3.z*SE[(cb+3)&7]));
    }
    __syncthreads();   // S-exchange reads done; feat e-region dead

    // ---- stage (pitch 68, in feat region) and coalesced write-out ----
    {
        float4* st = (float4*)(feat_sh + p*68 + part*16);
        #pragma unroll
        for (int i4 = 0; i4 < 4; ++i4)
            st[i4] = make_float4(va[4*i4], va[4*i4+1], va[4*i4+2], va[4*i4+3]);
    }
    __syncthreads();
    {
        float4* dst = (float4*)(out + (size_t)(batch*NPTS + tstart) * 64);
        for (int i = tid; i < T2*16; i += 256) {
            int pp = i >> 4, k4 = i & 15;
            dst[i] = ((const float4*)(feat_sh + pp*68))[k4];
        }
    }
}

extern "C" void kernel_launch(void* const* d_in, const int* in_sizes, int n_in,
                              void* d_out, int out_size)
{
    const float* points = (const float*)d_in[0];
    const float* feats  = (const float*)d_in[1];
    const float* Wq   = (const float*)d_in[2];
    const float* bq   = (const float*)d_in[3];
    const float* Wk   = (const float*)d_in[4];
    const float* bk   = (const float*)d_in[5];
    const float* Wv   = (const float*)d_in[6];
    const float* bv   = (const float*)d_in[7];
    const float* Wp1  = (const float*)d_in[8];
    const float* p_g  = (const float*)d_in[9];
    const float* p_b  = (const float*)d_in[10];
    const float* p_m  = (const float*)d_in[11];
    const float* p_v  = (const float*)d_in[12];
    const float* Wp2  = (const float*)d_in[13];
    const float* bp2  = (const float*)d_in[14];
    const float* w1_g = (const float*)d_in[15];
    const float* w1_b = (const float*)d_in[16];
    const float* w1_m = (const float*)d_in[17];
    const float* w1_v = (const float*)d_in[18];
    const float* Ww1  = (const float*)d_in[19];
    const float* w2_g = (const float*)d_in[20];
    const float* w2_b = (const float*)d_in[21];
    const float* w2_m = (const float*)d_in[22];
    const float* w2_v = (const float*)d_in[23];
    const float* Ww2  = (const float*)d_in[24];
    const float* bw2  = (const float*)d_in[25];
    float* out = (float*)d_out;

    const int smem_bytes = SMEM_FLOATS * (int)sizeof(float);   // ~54.7 KB
    cudaFuncSetAttribute(pt_fused64,
                         cudaFuncAttributeMaxDynamicSharedMemorySize, smem_bytes);

    const int nblocks = (4 * NPTS) / T2;   // 1024
    pt_fused64<<<nblocks, 256, smem_bytes>>>(
        points, feats, Wq, bq, Wk, bk, Wv, bv, Wp1,
        p_g, p_b, p_m, p_v, Wp2, bp2,
        w1_g, w1_b, w1_m, w1_v, Ww1,
        w2_g, w2_b, w2_m, w2_v, Ww2, bw2, out);
}

// round 11
// speedup vs baseline: 2.2286x; 2.0594x over previous
#include <cuda_runtime.h>

#define NPTS   16384
#define RAD    8
#define TILE   128
#define HALO   (TILE + 2*RAD)   // 144
#define QPITCH 100
#define OPITCH 68
#define SPITCH 49
#define EPSC   1e-5f
#define L2E    1.44269504088896340736f

// smem: feat 9216 (-> e-pairs / S-exchange / staging), qkv 14400, pts 288
#define SMEM_FLOATS (HALO*64 + HALO*QPITCH + HALO*2)

// folded constants: [0:32) cM2 | [32:64) cW2 | [64:80) cP0 | [80:96) cS
//                   [96:128) cE4 | [128:384) cR4 | [384:396) misc
__device__   __align__(16) float cFoldBuf[396];
__constant__ __align__(16) float cF[396];

#define PACK2(dst, lo, hi) asm("mov.b64 %0, {%1, %2};" : "=l"(dst) : "f"(lo), "f"(hi))
#define UNPACK2(lo, hi, v) asm("mov.b64 {%0, %1}, %2;" : "=f"(lo), "=f"(hi) : "l"(v))
#define FMA2(d, a, b, c)   asm("fma.rn.f32x2 %0, %1, %2, %3;" : "=l"(d) : "l"(a), "l"(b), "l"(c))

__global__ void prep_fold(const float* __restrict__ Wp1,
                          const float* __restrict__ p_g, const float* __restrict__ p_b,
                          const float* __restrict__ p_m, const float* __restrict__ p_v,
                          const float* __restrict__ Wp2, const float* __restrict__ bp2,
                          const float* __restrict__ w1_g, const float* __restrict__ w1_b,
                          const float* __restrict__ w1_m, const float* __restrict__ w1_v,
                          const float* __restrict__ Ww1,
                          const float* __restrict__ w2_g, const float* __restrict__ w2_b,
                          const float* __restrict__ w2_m, const float* __restrict__ w2_v,
                          const float* __restrict__ Ww2,  const float* __restrict__ bw2)
{
    const int tid = threadIdx.x;
    float* buf = cFoldBuf;
    if (tid < 64)
        ((float4*)(buf + 128))[tid] = make_float4(Wp2[tid], Wp2[64 + tid], bp2[tid], 0.f);
    if (tid < 16) {
        float As  = Wp2[tid]    + Wp2[16+tid] + Wp2[32+tid] + Wp2[48+tid];
        float Bs  = Wp2[64+tid] + Wp2[80+tid] + Wp2[96+tid] + Wp2[112+tid];
        float bps = bp2[tid] + bp2[16+tid] + bp2[32+tid] + bp2[48+tid];
        float s   = w1_g[tid] * rsqrtf(w1_v[tid] + EPSC);
        float w1beff = w1_b[tid] - w1_m[tid]*s;
        ((float2*)buf)[tid]        = make_float2(As*s, Bs*s);
        ((float2*)(buf + 32))[tid] = make_float2(Ww1[2*tid], Ww1[2*tid+1]);
        buf[64 + tid] = bps*s + w1beff;
        buf[80 + tid] = s;
    }
    if (tid < 8)
        ((float4*)(buf + 96))[tid] = make_float4(Ww2[tid]*L2E, Ww2[8+tid]*L2E, bw2[tid]*L2E, 0.f);
    if (tid < 2) {
        float s = p_g[tid] * rsqrtf(p_v[tid] + EPSC);
        buf[384+4+tid] = s; buf[384+6+tid] = p_b[tid] - p_m[tid]*s;
        float s2 = w2_g[tid] * rsqrtf(w2_v[tid] + EPSC);
        buf[384+8+tid] = s2; buf[384+10+tid] = w2_b[tid] - w2_m[tid]*s2;
    }
    if (tid < 4) buf[384 + tid] = Wp1[tid];
}

__global__ __launch_bounds__(256, 2)
void pt_fused_kernel(const float* __restrict__ points,
                     const float* __restrict__ features,
                     const float* __restrict__ Wq,  const float* __restrict__ bq,
                     const float* __restrict__ Wk,  const float* __restrict__ bk,
                     const float* __restrict__ Wv,  const float* __restrict__ bv,
                     float* __restrict__ out)
{
    extern __shared__ float sm[];
    float* scratch = sm;                        // 9216
    float* qkv_sh  = scratch + HALO*64;         // 14400
    float* pts_sh  = qkv_sh  + HALO*QPITCH;     // 288

    const float2* cM2  = (const float2*)cF;
    const float2* cW2  = (const float2*)(cF + 32);
    const float*  cP0  = cF + 64;
    const float*  cS   = cF + 80;
    const float4* cE4  = (const float4*)(cF + 96);
    const float4* cR4  = (const float4*)(cF + 128);
    const float*  misc = cF + 384;

    const int tid    = threadIdx.x;
    const int bidx   = blockIdx.x;
    const int batch  = bidx >> 7;
    const int tstart = (bidx & 127) * TILE;

    // ---- stage halo features + coords ----
    {
        const float4* fglob = (const float4*)features;
        for (int i = tid; i < HALO*16; i += 256) {
            int h = i >> 4, k4 = i & 15;
            int row = batch*NPTS + ((tstart + h - RAD) & (NPTS - 1));
            ((float4*)scratch)[h*16 + k4] = fglob[row*16 + k4];
        }
        const float2* pglob = (const float2*)points;
        for (int i = tid; i < HALO; i += 256) {
            int row = batch*NPTS + ((tstart + i - RAD) & (NPTS - 1));
            ((float2*)pts_sh)[i] = pglob[row];
        }
    }

    // ---- phase-1 weight preload: one channel column per lane, packed f32x2 ----
    const int warp = tid >> 5, lane = tid & 31;
    int cg, sub, npw;
    if (warp < 3)      { cg = 0; sub = warp;     npw = 3; }
    else if (warp < 6) { cg = 1; sub = warp - 3; npw = 3; }
    else               { cg = 2; sub = warp - 6; npw = 2; }
    const int c = cg*32 + lane;

    unsigned long long wp[32];
    float bias;
    if (c < 16) {
        bias = bq[c];
        #pragma unroll
        for (int i = 0; i < 32; ++i) PACK2(wp[i], Wq[(2*i)*16 + c], Wq[(2*i+1)*16 + c]);
    } else if (c < 32) {
        int cc = c - 16; bias = bk[cc];
        #pragma unroll
        for (int i = 0; i < 32; ++i) PACK2(wp[i], Wk[(2*i)*16 + cc], Wk[(2*i+1)*16 + cc]);
    } else {
        int cc = c - 32; bias = bv[cc];
        #pragma unroll
        for (int i = 0; i < 32; ++i) PACK2(wp[i], Wv[(2*i)*64 + cc], Wv[(2*i+1)*64 + cc]);
    }
    __syncthreads();

    const float chan_scale = (c < 32) ? cS[c & 15] : 1.0f;

    // ---- phase 1: q/k/v GEMM via fma.f32x2 -> qkv_sh[p*QPITCH + c] ----
    {
        const int span = HALO / npw;
        const int pend = (sub + 1) * span;
        #pragma unroll 2
        for (int p = sub * span; p < pend; ++p) {
            const ulonglong2* fr = (const ulonglong2*)(scratch + (p << 6));
            unsigned long long aA = 0ull, aB = 0ull, aC = 0ull, aD = 0ull;
            #pragma unroll
            for (int k2 = 0; k2 < 8; ++k2) {
                ulonglong2 f0 = fr[2*k2];
                ulonglong2 f1 = fr[2*k2 + 1];
                FMA2(aA, f0.x, wp[4*k2    ], aA);
                FMA2(aB, f0.y, wp[4*k2 + 1], aB);
                FMA2(aC, f1.x, wp[4*k2 + 2], aC);
                FMA2(aD, f1.y, wp[4*k2 + 3], aD);
            }
            float x0,x1,x2,x3,x4,x5,x6,x7;
            UNPACK2(x0,x1,aA); UNPACK2(x2,x3,aB); UNPACK2(x4,x5,aC); UNPACK2(x6,x7,aD);
            float s = ((x0+x1)+(x2+x3)) + ((x4+x5)+(x6+x7)) + bias;
            qkv_sh[p*QPITCH + c] = s * chan_scale;
        }
    }
    __syncthreads();

    // ---- phase 2 ----
    const int p    = tid & 127;
    const int half = tid >> 7;
    const int hme  = p + RAD;

    unsigned long long vacc2[16];
    #pragma unroll
    for (int i = 0; i < 16; ++i) vacc2[i] = 0ull;
    float S0[8], S1[8], SE[8];
    #pragma unroll
    for (int i = 0; i < 8; ++i) { S0[i] = 0.f; S1[i] = 0.f; SE[i] = 0.f; }

    const float W00 = misc[0], W01 = misc[1], W10 = misc[2], W11 = misc[3];
    const float ps0 = misc[4], ps1 = misc[5], pb0 = misc[6], pb1 = misc[7];
    const float w2s0 = misc[8], w2s1 = misc[9], w2b0 = misc[10], w2b1 = misc[11];

    #pragma unroll 1
    for (int chunk = 0; chunk < 2; ++chunk) {
        // ---- 2a: MLP+softmax once per (p, j); this thread: j = chunk*8 + 2k + half
        {
            const float2 pme = ((const float2*)pts_sh)[hme];
            float P[16];
            {
                const float4* q4 = (const float4*)(qkv_sh + hme*QPITCH);
                #pragma unroll
                for (int m4 = 0; m4 < 4; ++m4) {
                    float4 t = q4[m4];
                    P[4*m4  ] = cP0[4*m4  ] - t.x;
                    P[4*m4+1] = cP0[4*m4+1] - t.y;
                    P[4*m4+2] = cP0[4*m4+2] - t.z;
                    P[4*m4+3] = cP0[4*m4+3] - t.w;
                }
            }
            #pragma unroll 1
            for (int k = 0; k < 4; ++k) {
                const int jj  = chunk*8 + 2*k + half;
                const int off = jj - 8 + (jj >> 3);
                const int h   = hme + off;

                const float2 pn = ((const float2*)pts_sh)[h];
                const float dx = pn.x - pme.x;
                const float dy = pn.y - pme.y;
                const float h0 = fmaxf(fmaf(dx*W00 + dy*W10, ps0, pb0), 0.f);
                const float h1 = fmaxf(fmaf(dx*W01 + dy*W11, ps1, pb1), 0.f);

                float t0a = 0.f, t0b = 0.f, t1a = 0.f, t1b = 0.f;
                const float4* k4p = (const float4*)(qkv_sh + h*QPITCH + 16);
                const float4* m4p = (const float4*)cM2;
                const float4* w4p = (const float4*)cW2;
                #pragma unroll
                for (int m4 = 0; m4 < 4; ++m4) {
                    float4 kk = k4p[m4];
                    float4 ma = m4p[2*m4], mb = m4p[2*m4+1];
                    float4 wa = w4p[2*m4], wb = w4p[2*m4+1];
                    int m0 = 4*m4;
                    float wr0 = fmaxf(fmaf(h0, ma.x, fmaf(h1, ma.y, kk.x + P[m0  ])), 0.f);
                    float wr1 = fmaxf(fmaf(h0, ma.z, fmaf(h1, ma.w, kk.y + P[m0+1])), 0.f);
                    float wr2 = fmaxf(fmaf(h0, mb.x, fmaf(h1, mb.y, kk.z + P[m0+2])), 0.f);
                    float wr3 = fmaxf(fmaf(h0, mb.z, fmaf(h1, mb.w, kk.w + P[m0+3])), 0.f);
                    t0a = fmaf(wr0, wa.x, t0a);  t1a = fmaf(wr0, wa.y, t1a);
                    t0b = fmaf(wr1, wa.z, t0b);  t1b = fmaf(wr1, wa.w, t1b);
                    t0a = fmaf(wr2, wb.x, t0a);  t1a = fmaf(wr2, wb.y, t1a);
                    t0b = fmaf(wr3, wb.z, t0b);  t1b = fmaf(wr3, wb.w, t1b);
                }
                float t0 = t0a + t0b, t1 = t1a + t1b;
                t0 = fmaxf(fmaf(t0, w2s0, w2b0), 0.f);
                t1 = fmaxf(fmaf(t1, w2s1, w2b1), 0.f);

                float e[8];
                #pragma unroll
                for (int cc = 0; cc < 8; ++cc) {
                    float4 ce = cE4[cc];
                    e[cc] = fmaf(t0, ce.x, fmaf(t1, ce.y, ce.z));   // log2-domain
                }
                float mx = fmaxf(fmaxf(fmaxf(e[0],e[1]), fmaxf(e[2],e[3])),
                                 fmaxf(fmaxf(e[4],e[5]), fmaxf(e[6],e[7])));
                #pragma unroll
                for (int cc = 0; cc < 8; ++cc) e[cc] = exp2f(e[cc] - mx);
                float sA = (e[0]+e[1]) + (e[2]+e[3]);
                float sB = (e[4]+e[5]) + (e[6]+e[7]);
                const float inv = __fdividef(1.0f, sA + sB);
                #pragma unroll
                for (int cc = 0; cc < 8; ++cc) e[cc] *= inv;

                #pragma unroll
                for (int cc = 0; cc < 8; ++cc) {
                    S0[cc] = fmaf(h0, e[cc], S0[cc]);
                    S1[cc] = fmaf(h1, e[cc], S1[cc]);
                    SE[cc] += e[cc];
                }
                // store e pairs: u64 scratch[cpair*1024 + jr*128 + p]
                {
                    float2* ep = (float2*)scratch + (jj & 7)*128 + p;
                    ep[0]    = make_float2(e[0], e[1]);
                    ep[1024] = make_float2(e[2], e[3]);
                    ep[2048] = make_float2(e[4], e[5]);
                    ep[3072] = make_float2(e[6], e[7]);
                }
            }
        }
        __syncthreads();

        // ---- 2b: packed f32x2 weighted-v accumulation (32 channels/thread) ----
        #pragma unroll 2
        for (int jr = 0; jr < 8; ++jr) {
            const int jj  = chunk*8 + jr;
            const int off = jj - 8 + (jj >> 3);
            const int h   = hme + off;
            const unsigned long long* ep = (const unsigned long long*)scratch + jr*128 + p;
            unsigned long long e2[4];
            e2[0] = ep[0]; e2[1] = ep[1024]; e2[2] = ep[2048]; e2[3] = ep[3072];
            const ulonglong2* v2 = (const ulonglong2*)(qkv_sh + h*QPITCH + 32 + half*32);
            #pragma unroll
            for (int i = 0; i < 8; ++i) {
                ulonglong2 v = v2[i];
                FMA2(vacc2[2*i  ], v.x, e2[(2*i  ) & 3], vacc2[2*i  ]);
                FMA2(vacc2[2*i+1], v.y, e2[(2*i+1) & 3], vacc2[2*i+1]);
            }
        }
        __syncthreads();
    }

    // ---- unpack accumulators ----
    float va[32];
    #pragma unroll
    for (int t = 0; t < 16; ++t) UNPACK2(va[2*t], va[2*t+1], vacc2[t]);

    // ---- combine S partials across the two j-parity threads of this point ----
    {
        float* sp = scratch + p*SPITCH + half*24;
        #pragma unroll
        for (int i = 0; i < 8; ++i) { sp[i] = S0[i]; sp[8+i] = S1[i]; sp[16+i] = SE[i]; }
    }
    __syncthreads();
    {
        const float* so = scratch + p*SPITCH + (half^1)*24;
        #pragma unroll
        for (int i = 0; i < 8; ++i) { S0[i] += so[i]; S1[i] += so[8+i]; SE[i] += so[16+i]; }
    }
    // apply factored positional term
    #pragma unroll
    for (int c4 = 0; c4 < 8; ++c4) {
        int cb = half*32 + 4*c4;
        float4 r0 = cR4[cb], r1 = cR4[cb+1], r2 = cR4[cb+2], r3 = cR4[cb+3];
        va[c4*4  ] += fmaf(r0.x, S0[(c4*4  )&7], fmaf(r0.y, S1[(c4*4  )&7], r0.z*SE[(c4*4  )&7]));
        va[c4*4+1] += fmaf(r1.x, S0[(c4*4+1)&7], fmaf(r1.y, S1[(c4*4+1)&7], r1.z*SE[(c4*4+1)&7]));
        va[c4*4+2] += fmaf(r2.x, S0[(c4*4+2)&7], fmaf(r2.y, S1[(c4*4+2)&7], r2.z*SE[(c4*4+2)&7]));
        va[c4*4+3] += fmaf(r3.x, S0[(c4*4+3)&7], fmaf(r3.y, S1[(c4*4+3)&7], r3.z*SE[(c4*4+3)&7]));
    }
    __syncthreads();   // S-exchange reads done before staging overwrite

    // ---- stage (pitch 68) and coalesced write-out ----
    {
        float4* st = (float4*)(scratch + p*OPITCH + half*32);
        #pragma unroll
        for (int c4 = 0; c4 < 8; ++c4)
            st[c4] = make_float4(va[c4*4], va[c4*4+1], va[c4*4+2], va[c4*4+3]);
    }
    __syncthreads();
    {
        float4* dst = (float4*)(out + (size_t)(batch*NPTS + tstart) * 64);
        for (int i = tid; i < TILE*16; i += 256) {
            int pp = i >> 4, k4 = i & 15;
            dst[i] = ((const float4*)(scratch + pp*OPITCH))[k4];
        }
    }
}

extern "C" void kernel_launch(void* const* d_in, const int* in_sizes, int n_in,
                              void* d_out, int out_size)
{
    const float* points = (const float*)d_in[0];
    const float* feats  = (const float*)d_in[1];
    const float* Wq   = (const float*)d_in[2];
    const float* bq   = (const float*)d_in[3];
    const float* Wk   = (const float*)d_in[4];
    const float* bk   = (const float*)d_in[5];
    const float* Wv   = (const float*)d_in[6];
    const float* bv   = (const float*)d_in[7];
    const float* Wp1  = (const float*)d_in[8];
    const float* p_g  = (const float*)d_in[9];
    const float* p_b  = (const float*)d_in[10];
    const float* p_m  = (const float*)d_in[11];
    const float* p_v  = (const float*)d_in[12];
    const float* Wp2  = (const float*)d_in[13];
    const float* bp2  = (const float*)d_in[14];
    const float* w1_g = (const float*)d_in[15];
    const float* w1_b = (const float*)d_in[16];
    const float* w1_m = (const float*)d_in[17];
    const float* w1_v = (const float*)d_in[18];
    const float* Ww1  = (const float*)d_in[19];
    const float* w2_g = (const float*)d_in[20];
    const float* w2_b = (const float*)d_in[21];
    const float* w2_m = (const float*)d_in[22];
    const float* w2_v = (const float*)d_in[23];
    const float* Ww2  = (const float*)d_in[24];
    const float* bw2  = (const float*)d_in[25];
    float* out = (float*)d_out;

    // fold constants -> __device__ buffer -> __constant__ bank
    prep_fold<<<1, 64>>>(Wp1, p_g, p_b, p_m, p_v, Wp2, bp2,
                         w1_g, w1_b, w1_m, w1_v, Ww1,
                         w2_g, w2_b, w2_m, w2_v, Ww2, bw2);
    void* src = nullptr;
    cudaGetSymbolAddress(&src, cFoldBuf);
    cudaMemcpyToSymbolAsync(cF, src, 396 * sizeof(float), 0,
                            cudaMemcpyDeviceToDevice, 0);

    const int smem_bytes = SMEM_FLOATS * (int)sizeof(float);  // ~95.6 KB
    cudaFuncSetAttribute(pt_fused_kernel,
                         cudaFuncAttributeMaxDynamicSharedMemorySize, smem_bytes);

    const int nblocks = (4 * NPTS) / TILE;   // 512
    pt_fused_kernel<<<nblocks, 256, smem_bytes>>>(
        points, feats, Wq, bq, Wk, bk, Wv, bv, out);
}

// round 12
// speedup vs baseline: 2.2931x; 1.0289x over previous
#include <cuda_runtime.h>

#define NPTS   16384
#define RAD    8
#define TILE   128
#define HALO   (TILE + 2*RAD)   // 144
#define QPITCH 100
#define OPITCH 68
#define SPITCH 49
#define EPSC   1e-5f
#define L2E    1.44269504088896340736f

// smem: feat 9216 (-> e-pairs / S-exchange / staging), qkv 14400, pts 288
#define SMEM_FLOATS (HALO*64 + HALO*QPITCH + HALO*2)

// folded constants: [0:32) cM2 | [32:64) cW2 | [64:80) cP0 | [80:96) cS
//                   [96:128) cE4 | [128:384) cR4 | [384:396) misc
__device__   __align__(16) float cFoldBuf[396];
__constant__ __align__(16) float cF[396];

#define PACK2(dst, lo, hi) asm("mov.b64 %0, {%1, %2};" : "=l"(dst) : "f"(lo), "f"(hi))
#define UNPACK2(lo, hi, v) asm("mov.b64 {%0, %1}, %2;" : "=f"(lo), "=f"(hi) : "l"(v))
#define FMA2(d, a, b, c)   asm("fma.rn.f32x2 %0, %1, %2, %3;" : "=l"(d) : "l"(a), "l"(b), "l"(c))
#define ADD2(d, a, b)      asm("add.rn.f32x2 %0, %1, %2;" : "=l"(d) : "l"(a), "l"(b))

__global__ void prep_fold(const float* __restrict__ Wp1,
                          const float* __restrict__ p_g, const float* __restrict__ p_b,
                          const float* __restrict__ p_m, const float* __restrict__ p_v,
                          const float* __restrict__ Wp2, const float* __restrict__ bp2,
                          const float* __restrict__ w1_g, const float* __restrict__ w1_b,
                          const float* __restrict__ w1_m, const float* __restrict__ w1_v,
                          const float* __restrict__ Ww1,
                          const float* __restrict__ w2_g, const float* __restrict__ w2_b,
                          const float* __restrict__ w2_m, const float* __restrict__ w2_v,
                          const float* __restrict__ Ww2,  const float* __restrict__ bw2)
{
    const int tid = threadIdx.x;
    float* buf = cFoldBuf;
    if (tid < 64)
        ((float4*)(buf + 128))[tid] = make_float4(Wp2[tid], Wp2[64 + tid], bp2[tid], 0.f);
    if (tid < 16) {
        float As  = Wp2[tid]    + Wp2[16+tid] + Wp2[32+tid] + Wp2[48+tid];
        float Bs  = Wp2[64+tid] + Wp2[80+tid] + Wp2[96+tid] + Wp2[112+tid];
        float bps = bp2[tid] + bp2[16+tid] + bp2[32+tid] + bp2[48+tid];
        float s   = w1_g[tid] * rsqrtf(w1_v[tid] + EPSC);
        float w1beff = w1_b[tid] - w1_m[tid]*s;
        ((float2*)buf)[tid]        = make_float2(As*s, Bs*s);
        ((float2*)(buf + 32))[tid] = make_float2(Ww1[2*tid], Ww1[2*tid+1]);
        buf[64 + tid] = bps*s + w1beff;
        buf[80 + tid] = s;
    }
    if (tid < 8)
        ((float4*)(buf + 96))[tid] = make_float4(Ww2[tid]*L2E, Ww2[8+tid]*L2E, bw2[tid]*L2E, 0.f);
    if (tid < 2) {
        float s = p_g[tid] * rsqrtf(p_v[tid] + EPSC);
        buf[384+4+tid] = s; buf[384+6+tid] = p_b[tid] - p_m[tid]*s;
        float s2 = w2_g[tid] * rsqrtf(w2_v[tid] + EPSC);
        buf[384+8+tid] = s2; buf[384+10+tid] = w2_b[tid] - w2_m[tid]*s2;
    }
    if (tid < 4) buf[384 + tid] = Wp1[tid];
}

__global__ __launch_bounds__(256, 2)
void pt_fused_kernel(const float* __restrict__ points,
                     const float* __restrict__ features,
                     const float* __restrict__ Wq,  const float* __restrict__ bq,
                     const float* __restrict__ Wk,  const float* __restrict__ bk,
                     const float* __restrict__ Wv,  const float* __restrict__ bv,
                     float* __restrict__ out)
{
    extern __shared__ float sm[];
    float* scratch = sm;                        // 9216
    float* qkv_sh  = scratch + HALO*64;         // 14400
    float* pts_sh  = qkv_sh  + HALO*QPITCH;     // 288

    const float2* cM2  = (const float2*)cF;
    const float2* cW2  = (const float2*)(cF + 32);
    const float*  cP0  = cF + 64;
    const float*  cS   = cF + 80;
    const float4* cE4  = (const float4*)(cF + 96);
    const float4* cR4  = (const float4*)(cF + 128);
    const float*  misc = cF + 384;

    const int tid    = threadIdx.x;
    const int bidx   = blockIdx.x;
    const int batch  = bidx >> 7;
    const int tstart = (bidx & 127) * TILE;

    // ---- stage halo features + coords ----
    {
        const float4* fglob = (const float4*)features;
        for (int i = tid; i < HALO*16; i += 256) {
            int h = i >> 4, k4 = i & 15;
            int row = batch*NPTS + ((tstart + h - RAD) & (NPTS - 1));
            ((float4*)scratch)[h*16 + k4] = fglob[row*16 + k4];
        }
        const float2* pglob = (const float2*)points;
        for (int i = tid; i < HALO; i += 256) {
            int row = batch*NPTS + ((tstart + i - RAD) & (NPTS - 1));
            ((float2*)pts_sh)[i] = pglob[row];
        }
    }

    // ---- phase-1 weight preload: one channel column per lane, packed f32x2 ----
    const int warp = tid >> 5, lane = tid & 31;
    int cg, sub, npw;
    if (warp < 3)      { cg = 0; sub = warp;     npw = 3; }
    else if (warp < 6) { cg = 1; sub = warp - 3; npw = 3; }
    else               { cg = 2; sub = warp - 6; npw = 2; }
    const int c = cg*32 + lane;

    unsigned long long wp[32];
    float bias;
    if (c < 16) {
        bias = bq[c];
        #pragma unroll
        for (int i = 0; i < 32; ++i) PACK2(wp[i], Wq[(2*i)*16 + c], Wq[(2*i+1)*16 + c]);
    } else if (c < 32) {
        int cc = c - 16; bias = bk[cc];
        #pragma unroll
        for (int i = 0; i < 32; ++i) PACK2(wp[i], Wk[(2*i)*16 + cc], Wk[(2*i+1)*16 + cc]);
    } else {
        int cc = c - 32; bias = bv[cc];
        #pragma unroll
        for (int i = 0; i < 32; ++i) PACK2(wp[i], Wv[(2*i)*64 + cc], Wv[(2*i+1)*64 + cc]);
    }
    __syncthreads();

    const float chan_scale = (c < 32) ? cS[c & 15] : 1.0f;
    const float sbias = bias * chan_scale;

    // ---- phase 1: q/k/v GEMM via fma.f32x2 -> qkv_sh[p*QPITCH + c] ----
    {
        const int span = HALO / npw;
        const int pend = (sub + 1) * span;
        #pragma unroll 2
        for (int p = sub * span; p < pend; ++p) {
            const ulonglong2* fr = (const ulonglong2*)(scratch + (p << 6));
            unsigned long long aA = 0ull, aB = 0ull, aC = 0ull, aD = 0ull;
            #pragma unroll
            for (int k2 = 0; k2 < 8; ++k2) {
                ulonglong2 f0 = fr[2*k2];
                ulonglong2 f1 = fr[2*k2 + 1];
                FMA2(aA, f0.x, wp[4*k2    ], aA);
                FMA2(aB, f0.y, wp[4*k2 + 1], aB);
                FMA2(aC, f1.x, wp[4*k2 + 2], aC);
                FMA2(aD, f1.y, wp[4*k2 + 3], aD);
            }
            unsigned long long u, v2r;
            ADD2(u, aA, aB); ADD2(v2r, aC, aD); ADD2(u, u, v2r);
            float lo, hi; UNPACK2(lo, hi, u);
            qkv_sh[p*QPITCH + c] = fmaf(lo + hi, chan_scale, sbias);
        }
    }
    __syncthreads();

    // ---- phase 2 ----
    const int p    = tid & 127;
    const int half = tid >> 7;
    const int hme  = p + RAD;

    unsigned long long vacc2[16];
    #pragma unroll
    for (int i = 0; i < 16; ++i) vacc2[i] = 0ull;
    float S0[8], S1[8], SE[8];
    #pragma unroll
    for (int i = 0; i < 8; ++i) { S0[i] = 0.f; S1[i] = 0.f; SE[i] = 0.f; }

    const float W00 = misc[0], W01 = misc[1], W10 = misc[2], W11 = misc[3];
    const float ps0 = misc[4], ps1 = misc[5], pb0 = misc[6], pb1 = misc[7];
    const float w2s0 = misc[8], w2s1 = misc[9], w2b0 = misc[10], w2b1 = misc[11];

    #pragma unroll 1
    for (int chunk = 0; chunk < 2; ++chunk) {
        // ---- 2a: MLP+softmax once per (p, j); this thread: j = chunk*8 + 2k + half
        {
            const float2 pme = ((const float2*)pts_sh)[hme];
            float P[16];
            {
                const float4* q4 = (const float4*)(qkv_sh + hme*QPITCH);
                #pragma unroll
                for (int m4 = 0; m4 < 4; ++m4) {
                    float4 t = q4[m4];
                    P[4*m4  ] = cP0[4*m4  ] - t.x;
                    P[4*m4+1] = cP0[4*m4+1] - t.y;
                    P[4*m4+2] = cP0[4*m4+2] - t.z;
                    P[4*m4+3] = cP0[4*m4+3] - t.w;
                }
            }
            #pragma unroll 1
            for (int k = 0; k < 4; ++k) {
                const int jj  = chunk*8 + 2*k + half;
                const int off = jj - 8 + (jj >> 3);
                const int h   = hme + off;

                const float2 pn = ((const float2*)pts_sh)[h];
                const float dx = pn.x - pme.x;
                const float dy = pn.y - pme.y;
                const float h0 = fmaxf(fmaf(dx*W00 + dy*W10, ps0, pb0), 0.f);
                const float h1 = fmaxf(fmaf(dx*W01 + dy*W11, ps1, pb1), 0.f);

                float t0a = 0.f, t0b = 0.f, t1a = 0.f, t1b = 0.f;
                const float4* k4p = (const float4*)(qkv_sh + h*QPITCH + 16);
                const float4* m4p = (const float4*)cM2;
                const float4* w4p = (const float4*)cW2;
                #pragma unroll
                for (int m4 = 0; m4 < 4; ++m4) {
                    float4 kk = k4p[m4];
                    float4 ma = m4p[2*m4], mb = m4p[2*m4+1];
                    float4 wa = w4p[2*m4], wb = w4p[2*m4+1];
                    int m0 = 4*m4;
                    float wr0 = fmaxf(fmaf(h0, ma.x, fmaf(h1, ma.y, kk.x + P[m0  ])), 0.f);
                    float wr1 = fmaxf(fmaf(h0, ma.z, fmaf(h1, ma.w, kk.y + P[m0+1])), 0.f);
                    float wr2 = fmaxf(fmaf(h0, mb.x, fmaf(h1, mb.y, kk.z + P[m0+2])), 0.f);
                    float wr3 = fmaxf(fmaf(h0, mb.z, fmaf(h1, mb.w, kk.w + P[m0+3])), 0.f);
                    t0a = fmaf(wr0, wa.x, t0a);  t1a = fmaf(wr0, wa.y, t1a);
                    t0b = fmaf(wr1, wa.z, t0b);  t1b = fmaf(wr1, wa.w, t1b);
                    t0a = fmaf(wr2, wb.x, t0a);  t1a = fmaf(wr2, wb.y, t1a);
                    t0b = fmaf(wr3, wb.z, t0b);  t1b = fmaf(wr3, wb.w, t1b);
                }
                float t0 = t0a + t0b, t1 = t1a + t1b;
                t0 = fmaxf(fmaf(t0, w2s0, w2b0), 0.f);
                t1 = fmaxf(fmaf(t1, w2s1, w2b1), 0.f);

                // softmax in log2 domain; logits bounded -> no max-shift needed
                float e[8];
                #pragma unroll
                for (int cc = 0; cc < 8; ++cc) {
                    float4 ce = cE4[cc];
                    e[cc] = exp2f(fmaf(t0, ce.x, fmaf(t1, ce.y, ce.z)));
                }
                float sA = (e[0]+e[1]) + (e[2]+e[3]);
                float sB = (e[4]+e[5]) + (e[6]+e[7]);
                const float inv = __fdividef(1.0f, sA + sB);
                #pragma unroll
                for (int cc = 0; cc < 8; ++cc) e[cc] *= inv;

                #pragma unroll
                for (int cc = 0; cc < 8; ++cc) {
                    S0[cc] = fmaf(h0, e[cc], S0[cc]);
                    S1[cc] = fmaf(h1, e[cc], S1[cc]);
                    SE[cc] += e[cc];
                }
                // store e pairs: u64 scratch[cpair*1024 + jr*128 + p]
                {
                    float2* ep = (float2*)scratch + (jj & 7)*128 + p;
                    ep[0]    = make_float2(e[0], e[1]);
                    ep[1024] = make_float2(e[2], e[3]);
                    ep[2048] = make_float2(e[4], e[5]);
                    ep[3072] = make_float2(e[6], e[7]);
                }
            }
        }
        __syncthreads();

        // ---- 2b: packed f32x2 weighted-v accumulation (32 channels/thread) ----
        #pragma unroll 2
        for (int jr = 0; jr < 8; ++jr) {
            const int jj  = chunk*8 + jr;
            const int off = jj - 8 + (jj >> 3);
            const int h   = hme + off;
            const unsigned long long* ep = (const unsigned long long*)scratch + jr*128 + p;
            unsigned long long e2[4];
            e2[0] = ep[0]; e2[1] = ep[1024]; e2[2] = ep[2048]; e2[3] = ep[3072];
            const ulonglong2* v2 = (const ulonglong2*)(qkv_sh + h*QPITCH + 32 + half*32);
            #pragma unroll
            for (int i = 0; i < 8; ++i) {
                ulonglong2 v = v2[i];
                FMA2(vacc2[2*i  ], v.x, e2[(2*i  ) & 3], vacc2[2*i  ]);
                FMA2(vacc2[2*i+1], v.y, e2[(2*i+1) & 3], vacc2[2*i+1]);
            }
        }
        __syncthreads();
    }

    // ---- unpack accumulators ----
    float va[32];
    #pragma unroll
    for (int t = 0; t < 16; ++t) UNPACK2(va[2*t], va[2*t+1], vacc2[t]);

    // ---- combine S partials across the two j-parity threads of this point ----
    {
        float* sp = scratch + p*SPITCH + half*24;
        #pragma unroll
        for (int i = 0; i < 8; ++i) { sp[i] = S0[i]; sp[8+i] = S1[i]; sp[16+i] = SE[i]; }
    }
    __syncthreads();
    {
        const float* so = scratch + p*SPITCH + (half^1)*24;
        #pragma unroll
        for (int i = 0; i < 8; ++i) { S0[i] += so[i]; S1[i] += so[8+i]; SE[i] += so[16+i]; }
    }
    // apply factored positional term
    #pragma unroll
    for (int c4 = 0; c4 < 8; ++c4) {
        int cb = half*32 + 4*c4;
        float4 r0 = cR4[cb], r1 = cR4[cb+1], r2 = cR4[cb+2], r3 = cR4[cb+3];
        va[c4*4  ] += fmaf(r0.x, S0[(c4*4  )&7], fmaf(r0.y, S1[(c4*4  )&7], r0.z*SE[(c4*4  )&7]));
        va[c4*4+1] += fmaf(r1.x, S0[(c4*4+1)&7], fmaf(r1.y, S1[(c4*4+1)&7], r1.z*SE[(c4*4+1)&7]));
        va[c4*4+2] += fmaf(r2.x, S0[(c4*4+2)&7], fmaf(r2.y, S1[(c4*4+2)&7], r2.z*SE[(c4*4+2)&7]));
        va[c4*4+3] += fmaf(r3.x, S0[(c4*4+3)&7], fmaf(r3.y, S1[(c4*4+3)&7], r3.z*SE[(c4*4+3)&7]));
    }
    __syncthreads();   // S-exchange reads done before staging overwrite

    // ---- stage (pitch 68) and coalesced write-out ----
    {
        float4* st = (float4*)(scratch + p*OPITCH + half*32);
        #pragma unroll
        for (int c4 = 0; c4 < 8; ++c4)
            st[c4] = make_float4(va[c4*4], va[c4*4+1], va[c4*4+2], va[c4*4+3]);
    }
    __syncthreads();
    {
        float4* dst = (float4*)(out + (size_t)(batch*NPTS + tstart) * 64);
        for (int i = tid; i < TILE*16; i += 256) {
            int pp = i >> 4, k4 = i & 15;
            dst[i] = ((const float4*)(scratch + pp*OPITCH))[k4];
        }
    }
}

extern "C" void kernel_launch(void* const* d_in, const int* in_sizes, int n_in,
                              void* d_out, int out_size)
{
    const float* points = (const float*)d_in[0];
    const float* feats  = (const float*)d_in[1];
    const float* Wq   = (const float*)d_in[2];
    const float* bq   = (const float*)d_in[3];
    const float* Wk   = (const float*)d_in[4];
    const float* bk   = (const float*)d_in[5];
    const float* Wv   = (const float*)d_in[6];
    const float* bv   = (const float*)d_in[7];
    const float* Wp1  = (const float*)d_in[8];
    const float* p_g  = (const float*)d_in[9];
    const float* p_b  = (const float*)d_in[10];
    const float* p_m  = (const float*)d_in[11];
    const float* p_v  = (const float*)d_in[12];
    const float* Wp2  = (const float*)d_in[13];
    const float* bp2  = (const float*)d_in[14];
    const float* w1_g = (const float*)d_in[15];
    const float* w1_b = (const float*)d_in[16];
    const float* w1_m = (const float*)d_in[17];
    const float* w1_v = (const float*)d_in[18];
    const float* Ww1  = (const float*)d_in[19];
    const float* w2_g = (const float*)d_in[20];
    const float* w2_b = (const float*)d_in[21];
    const float* w2_m = (const float*)d_in[22];
    const float* w2_v = (const float*)d_in[23];
    const float* Ww2  = (const float*)d_in[24];
    const float* bw2  = (const float*)d_in[25];
    float* out = (float*)d_out;

    // fold constants -> __device__ buffer -> __constant__ bank
    prep_fold<<<1, 64>>>(Wp1, p_g, p_b, p_m, p_v, Wp2, bp2,
                         w1_g, w1_b, w1_m, w1_v, Ww1,
                         w2_g, w2_b, w2_m, w2_v, Ww2, bw2);
    void* src = nullptr;
    cudaGetSymbolAddress(&src, cFoldBuf);
    cudaMemcpyToSymbolAsync(cF, src, 396 * sizeof(float), 0,
                            cudaMemcpyDeviceToDevice, 0);

    const int smem_bytes = SMEM_FLOATS * (int)sizeof(float);  // ~95.6 KB
    cudaFuncSetAttribute(pt_fused_kernel,
                         cudaFuncAttributeMaxDynamicSharedMemorySize, smem_bytes);

    const int nblocks = (4 * NPTS) / TILE;   // 512
    pt_fused_kernel<<<nblocks, 256, smem_bytes>>>(
        points, feats, Wq, bq, Wk, bk, Wv, bv, out);
}

// round 14
// speedup vs baseline: 2.4304x; 1.0599x over previous
#include <cuda_runtime.h>

#define NPTS   16384
#define RAD    8
#define QPITCH 100
#define OPITCH 68
#define SPITCH 49
#define EPSC   1e-5f
#define L2E    1.44269504088896340736f

#define NTILES 148           // tiles per batch == SM count
#define TBASE  110           // 104 tiles of 111 + 44 tiles of 110 = 16384
#define TREM   104
#define HALMAX 127           // 111 + 2*RAD

// smem: scratch 8192 (feat/e-pairs/S-exchange/staging), qkv 12700, pts 256
#define SMEM_FLOATS (8192 + HALMAX*QPITCH + 256)

__device__   __align__(16) float cFoldBuf[396];
__constant__ __align__(16) float cF[396];

#define PACK2(dst, lo, hi) asm("mov.b64 %0, {%1, %2};" : "=l"(dst) : "f"(lo), "f"(hi))
#define UNPACK2(lo, hi, v) asm("mov.b64 {%0, %1}, %2;" : "=f"(lo), "=f"(hi) : "l"(v))
#define FMA2(d, a, b, c)   asm("fma.rn.f32x2 %0, %1, %2, %3;" : "=l"(d) : "l"(a), "l"(b), "l"(c))
#define ADD2(d, a, b)      asm("add.rn.f32x2 %0, %1, %2;" : "=l"(d) : "l"(a), "l"(b))

__global__ void prep_fold(const float* __restrict__ Wp1,
                          const float* __restrict__ p_g, const float* __restrict__ p_b,
                          const float* __restrict__ p_m, const float* __restrict__ p_v,
                          const float* __restrict__ Wp2, const float* __restrict__ bp2,
                          const float* __restrict__ w1_g, const float* __restrict__ w1_b,
                          const float* __restrict__ w1_m, const float* __restrict__ w1_v,
                          const float* __restrict__ Ww1,
                          const float* __restrict__ w2_g, const float* __restrict__ w2_b,
                          const float* __restrict__ w2_m, const float* __restrict__ w2_v,
                          const float* __restrict__ Ww2,  const float* __restrict__ bw2)
{
    const int tid = threadIdx.x;
    float* buf = cFoldBuf;
    if (tid < 64)
        ((float4*)(buf + 128))[tid] = make_float4(Wp2[tid], Wp2[64 + tid], bp2[tid], 0.f);
    if (tid < 16) {
        float As  = Wp2[tid]    + Wp2[16+tid] + Wp2[32+tid] + Wp2[48+tid];
        float Bs  = Wp2[64+tid] + Wp2[80+tid] + Wp2[96+tid] + Wp2[112+tid];
        float bps = bp2[tid] + bp2[16+tid] + bp2[32+tid] + bp2[48+tid];
        float s   = w1_g[tid] * rsqrtf(w1_v[tid] + EPSC);
        float w1beff = w1_b[tid] - w1_m[tid]*s;
        ((float2*)buf)[tid]        = make_float2(As*s, Bs*s);
        ((float2*)(buf + 32))[tid] = make_float2(Ww1[2*tid], Ww1[2*tid+1]);
        buf[64 + tid] = bps*s + w1beff;
        buf[80 + tid] = s;
    }
    if (tid < 8)
        ((float4*)(buf + 96))[tid] = make_float4(Ww2[tid]*L2E, Ww2[8+tid]*L2E, bw2[tid]*L2E, 0.f);
    if (tid < 2) {
        float s = p_g[tid] * rsqrtf(p_v[tid] + EPSC);
        buf[384+4+tid] = s; buf[384+6+tid] = p_b[tid] - p_m[tid]*s;
        float s2 = w2_g[tid] * rsqrtf(w2_v[tid] + EPSC);
        buf[384+8+tid] = s2; buf[384+10+tid] = w2_b[tid] - w2_m[tid]*s2;
    }
    if (tid < 4) buf[384 + tid] = Wp1[tid];
}

__global__ __launch_bounds__(256, 2)
void pt_fused_kernel(const float* __restrict__ points,
                     const float* __restrict__ features,
                     const float* __restrict__ Wq,  const float* __restrict__ bq,
                     const float* __restrict__ Wk,  const float* __restrict__ bk,
                     const float* __restrict__ Wv,  const float* __restrict__ bv,
                     float* __restrict__ out)
{
    extern __shared__ float sm[];
    float* scratch = sm;                        // 8192: feat -> e-pairs -> S -> staging
    float* qkv_sh  = scratch + 8192;            // 12700
    float* pts_sh  = qkv_sh  + HALMAX*QPITCH;   // 256

    const float2* cM2  = (const float2*)cF;
    const float2* cW2  = (const float2*)(cF + 32);
    const float*  cP0  = cF + 64;
    const float*  cS   = cF + 80;
    const float4* cE4  = (const float4*)(cF + 96);
    const float4* cR4  = (const float4*)(cF + 128);
    const float*  misc = cF + 384;

    const int tid    = threadIdx.x;
    const int bidx   = blockIdx.x;
    const int batch  = bidx / NTILES;
    const int ti     = bidx - batch * NTILES;
    const int tsz    = (ti < TREM) ? (TBASE + 1) : TBASE;
    const int tstart = ti * TBASE + ((ti < TREM) ? ti : TREM);
    const int hal    = tsz + 2*RAD;             // 126 or 127

    // ---- stage halo features + coords ----
    {
        const float4* fglob = (const float4*)features;
        for (int i = tid; i < hal*16; i += 256) {
            int h = i >> 4, k4 = i & 15;
            int row = batch*NPTS + ((tstart + h - RAD) & (NPTS - 1));
            ((float4*)scratch)[h*16 + k4] = fglob[row*16 + k4];
        }
        const float2* pglob = (const float2*)points;
        for (int i = tid; i < hal; i += 256) {
            int row = batch*NPTS + ((tstart + i - RAD) & (NPTS - 1));
            ((float2*)pts_sh)[i] = pglob[row];
        }
    }

    // ---- phase-1 weight preload: one channel column per lane, packed f32x2 ----
    const int warp = tid >> 5, lane = tid & 31;
    int cg, sub, npw;
    if (warp < 3)      { cg = 0; sub = warp;     npw = 3; }
    else if (warp < 6) { cg = 1; sub = warp - 3; npw = 3; }
    else               { cg = 2; sub = warp - 6; npw = 2; }
    const int c = cg*32 + lane;

    unsigned long long wp[32];
    float bias;
    if (c < 16) {
        bias = bq[c];
        #pragma unroll
        for (int i = 0; i < 32; ++i) PACK2(wp[i], Wq[(2*i)*16 + c], Wq[(2*i+1)*16 + c]);
    } else if (c < 32) {
        int cc = c - 16; bias = bk[cc];
        #pragma unroll
        for (int i = 0; i < 32; ++i) PACK2(wp[i], Wk[(2*i)*16 + cc], Wk[(2*i+1)*16 + cc]);
    } else {
        int cc = c - 32; bias = bv[cc];
        #pragma unroll
        for (int i = 0; i < 32; ++i) PACK2(wp[i], Wv[(2*i)*64 + cc], Wv[(2*i+1)*64 + cc]);
    }
    __syncthreads();

    const float chan_scale = (c < 32) ? cS[c & 15] : 1.0f;
    const float sbias = bias * chan_scale;

    // ---- phase 1: q/k/v GEMM over hal rows -> qkv_sh[p*QPITCH + c] ----
    {
        const int pbeg = (sub * hal) / npw;
        const int pend = ((sub + 1) * hal) / npw;
        #pragma unroll 2
        for (int p = pbeg; p < pend; ++p) {
            const ulonglong2* fr = (const ulonglong2*)(scratch + (p << 6));
            unsigned long long aA = 0ull, aB = 0ull, aC = 0ull, aD = 0ull;
            #pragma unroll
            for (int k2 = 0; k2 < 8; ++k2) {
                ulonglong2 f0 = fr[2*k2];
                ulonglong2 f1 = fr[2*k2 + 1];
                FMA2(aA, f0.x, wp[4*k2    ], aA);
                FMA2(aB, f0.y, wp[4*k2 + 1], aB);
                FMA2(aC, f1.x, wp[4*k2 + 2], aC);
                FMA2(aD, f1.y, wp[4*k2 + 3], aD);
            }
            unsigned long long u, v2r;
            ADD2(u, aA, aB); ADD2(v2r, aC, aD); ADD2(u, u, v2r);
            float lo, hi; UNPACK2(lo, hi, u);
            qkv_sh[p*QPITCH + c] = fmaf(lo + hi, chan_scale, sbias);
        }
    }
    __syncthreads();

    // ---- phase 2 (threads with p_raw >= tsz clamp and duplicate point tsz-1) ----
    const int p_raw = tid & 127;
    const int half  = tid >> 7;
    const int p     = (p_raw < tsz) ? p_raw : (tsz - 1);
    const int hme   = p + RAD;

    unsigned long long vacc2[16];
    #pragma unroll
    for (int i = 0; i < 16; ++i) vacc2[i] = 0ull;
    float S0[8], S1[8], SE[8];
    #pragma unroll
    for (int i = 0; i < 8; ++i) { S0[i] = 0.f; S1[i] = 0.f; SE[i] = 0.f; }

    const float W00 = misc[0], W01 = misc[1], W10 = misc[2], W11 = misc[3];
    const float ps0 = misc[4], ps1 = misc[5], pb0 = misc[6], pb1 = misc[7];
    const float w2s0 = misc[8], w2s1 = misc[9], w2b0 = misc[10], w2b1 = misc[11];

    #pragma unroll 1
    for (int chunk = 0; chunk < 2; ++chunk) {
        // ---- 2a: MLP+softmax once per (p, j); this thread: j = chunk*8 + 2k + half
        {
            const float2 pme = ((const float2*)pts_sh)[hme];
            float P[16];
            {
                const float4* q4 = (const float4*)(qkv_sh + hme*QPITCH);
                #pragma unroll
                for (int m4 = 0; m4 < 4; ++m4) {
                    float4 t = q4[m4];
                    P[4*m4  ] = cP0[4*m4  ] - t.x;
                    P[4*m4+1] = cP0[4*m4+1] - t.y;
                    P[4*m4+2] = cP0[4*m4+2] - t.z;
                    P[4*m4+3] = cP0[4*m4+3] - t.w;
                }
            }
            #pragma unroll 1
            for (int k = 0; k < 4; ++k) {
                const int jj  = chunk*8 + 2*k + half;
                const int off = jj - 8 + (jj >> 3);
                const int h   = hme + off;

                const float2 pn = ((const float2*)pts_sh)[h];
                const float dx = pn.x - pme.x;
                const float dy = pn.y - pme.y;
                const float h0 = fmaxf(fmaf(dx*W00 + dy*W10, ps0, pb0), 0.f);
                const float h1 = fmaxf(fmaf(dx*W01 + dy*W11, ps1, pb1), 0.f);

                float t0a = 0.f, t0b = 0.f, t1a = 0.f, t1b = 0.f;
                const float4* k4p = (const float4*)(qkv_sh + h*QPITCH + 16);
                const float4* m4p = (const float4*)cM2;
                const float4* w4p = (const float4*)cW2;
                #pragma unroll
                for (int m4 = 0; m4 < 4; ++m4) {
                    float4 kk = k4p[m4];
                    float4 ma = m4p[2*m4], mb = m4p[2*m4+1];
                    float4 wa = w4p[2*m4], wb = w4p[2*m4+1];
                    int m0 = 4*m4;
                    float wr0 = fmaxf(fmaf(h0, ma.x, fmaf(h1, ma.y, kk.x + P[m0  ])), 0.f);
                    float wr1 = fmaxf(fmaf(h0, ma.z, fmaf(h1, ma.w, kk.y + P[m0+1])), 0.f);
                    float wr2 = fmaxf(fmaf(h0, mb.x, fmaf(h1, mb.y, kk.z + P[m0+2])), 0.f);
                    float wr3 = fmaxf(fmaf(h0, mb.z, fmaf(h1, mb.w, kk.w + P[m0+3])), 0.f);
                    t0a = fmaf(wr0, wa.x, t0a);  t1a = fmaf(wr0, wa.y, t1a);
                    t0b = fmaf(wr1, wa.z, t0b);  t1b = fmaf(wr1, wa.w, t1b);
                    t0a = fmaf(wr2, wb.x, t0a);  t1a = fmaf(wr2, wb.y, t1a);
                    t0b = fmaf(wr3, wb.z, t0b);  t1b = fmaf(wr3, wb.w, t1b);
                }
                float t0 = t0a + t0b, t1 = t1a + t1b;
                t0 = fmaxf(fmaf(t0, w2s0, w2b0), 0.f);
                t1 = fmaxf(fmaf(t1, w2s1, w2b1), 0.f);

                // softmax in log2 domain; logits bounded -> no max-shift needed
                float e[8];
                #pragma unroll
                for (int cc = 0; cc < 8; ++cc) {
                    float4 ce = cE4[cc];
                    e[cc] = exp2f(fmaf(t0, ce.x, fmaf(t1, ce.y, ce.z)));
                }
                float sA = (e[0]+e[1]) + (e[2]+e[3]);
                float sB = (e[4]+e[5]) + (e[6]+e[7]);
                const float inv = __fdividef(1.0f, sA + sB);
                #pragma unroll
                for (int cc = 0; cc < 8; ++cc) e[cc] *= inv;

                #pragma unroll
                for (int cc = 0; cc < 8; ++cc) {
                    S0[cc] = fmaf(h0, e[cc], S0[cc]);
                    S1[cc] = fmaf(h1, e[cc], S1[cc]);
                    SE[cc] += e[cc];
                }
                // store e pairs: u64 scratch[cpair*1024 + jr*128 + p]
                {
                    float2* ep = (float2*)scratch + (jj & 7)*128 + p;
                    ep[0]    = make_float2(e[0], e[1]);
                    ep[1024] = make_float2(e[2], e[3]);
                    ep[2048] = make_float2(e[4], e[5]);
                    ep[3072] = make_float2(e[6], e[7]);
                }
            }
        }
        __syncthreads();

        // ---- 2b: packed f32x2 weighted-v accumulation (32 channels/thread) ----
        #pragma unroll 2
        for (int jr = 0; jr < 8; ++jr) {
            const int jj  = chunk*8 + jr;
            const int off = jj - 8 + (jj >> 3);
            const int h   = hme + off;
            const unsigned long long* ep = (const unsigned long long*)scratch + jr*128 + p;
            unsigned long long e2[4];
            e2[0] = ep[0]; e2[1] = ep[1024]; e2[2] = ep[2048]; e2[3] = ep[3072];
            const ulonglong2* v2 = (const ulonglong2*)(qkv_sh + h*QPITCH + 32 + half*32);
            #pragma unroll
            for (int i = 0; i < 8; ++i) {
                ulonglong2 v = v2[i];
                FMA2(vacc2[2*i  ], v.x, e2[(2*i  ) & 3], vacc2[2*i  ]);
                FMA2(vacc2[2*i+1], v.y, e2[(2*i+1) & 3], vacc2[2*i+1]);
            }
        }
        __syncthreads();
    }

    // ---- unpack accumulators ----
    float va[32];
    #pragma unroll
    for (int t = 0; t < 16; ++t) UNPACK2(va[2*t], va[2*t+1], vacc2[t]);

    // ---- combine S partials across the two j-parity threads of this point ----
    {
        float* sp = scratch + p*SPITCH + half*24;
        #pragma unroll
        for (int i = 0; i < 8; ++i) { sp[i] = S0[i]; sp[8+i] = S1[i]; sp[16+i] = SE[i]; }
    }
    __syncthreads();
    {
        const float* so = scratch + p*SPITCH + (half^1)*24;
        #pragma unroll
        for (int i = 0; i < 8; ++i) { S0[i] += so[i]; S1[i] += so[8+i]; SE[i] += so[16+i]; }
    }
    // apply factored positional term
    #pragma unroll
    for (int c4 = 0; c4 < 8; ++c4) {
        int cb = half*32 + 4*c4;
        float4 r0 = cR4[cb], r1 = cR4[cb+1], r2 = cR4[cb+2], r3 = cR4[cb+3];
        va[c4*4  ] += fmaf(r0.x, S0[(c4*4  )&7], fmaf(r0.y, S1[(c4*4  )&7], r0.z*SE[(c4*4  )&7]));
        va[c4*4+1] += fmaf(r1.x, S0[(c4*4+1)&7], fmaf(r1.y, S1[(c4*4+1)&7], r1.z*SE[(c4*4+1)&7]));
        va[c4*4+2] += fmaf(r2.x, S0[(c4*4+2)&7], fmaf(r2.y, S1[(c4*4+2)&7], r2.z*SE[(c4*4+2)&7]));
        va[c4*4+3] += fmaf(r3.x, S0[(c4*4+3)&7], fmaf(r3.y, S1[(c4*4+3)&7], r3.z*SE[(c4*4+3)&7]));
    }
    __syncthreads();   // S-exchange reads done before staging overwrite

    // ---- stage (pitch 68) and coalesced write-out ----
    {
        float4* st = (float4*)(scratch + p*OPITCH + half*32);
        #pragma unroll
        for (int c4 = 0; c4 < 8; ++c4)
            st[c4] = make_float4(va[c4*4], va[c4*4+1], va[c4*4+2], va[c4*4+3]);
    }
    __syncthreads();
    {
        float4* dst = (float4*)(out + (size_t)(batch*NPTS + tstart) * 64);
        for (int i = tid; i < tsz*16; i += 256) {
            int pp = i >> 4, k4 = i & 15;
            dst[i] = ((const float4*)(scratch + pp*OPITCH))[k4];
        }
    }
}

extern "C" void kernel_launch(void* const* d_in, const int* in_sizes, int n_in,
                              void* d_out, int out_size)
{
    const float* points = (const float*)d_in[0];
    const float* feats  = (const float*)d_in[1];
    const float* Wq   = (const float*)d_in[2];
    const float* bq   = (const float*)d_in[3];
    const float* Wk   = (const float*)d_in[4];
    const float* bk   = (const float*)d_in[5];
    const float* Wv   = (const float*)d_in[6];
    const float* bv   = (const float*)d_in[7];
    const float* Wp1  = (const float*)d_in[8];
    const float* p_g  = (const float*)d_in[9];
    const float* p_b  = (const float*)d_in[10];
    const float* p_m  = (const float*)d_in[11];
    const float* p_v  = (const float*)d_in[12];
    const float* Wp2  = (const float*)d_in[13];
    const float* bp2  = (const float*)d_in[14];
    const float* w1_g = (const float*)d_in[15];
    const float* w1_b = (const float*)d_in[16];
    const float* w1_m = (const float*)d_in[17];
    const float* w1_v = (const float*)d_in[18];
    const float* Ww1  = (const float*)d_in[19];
    const float* w2_g = (const float*)d_in[20];
    const float* w2_b = (const float*)d_in[21];
    const float* w2_m = (const float*)d_in[22];
    const float* w2_v = (const float*)d_in[23];
    const float* Ww2  = (const float*)d_in[24];
    const float* bw2  = (const float*)d_in[25];
    float* out = (float*)d_out;

    // fold constants -> __device__ buffer -> __constant__ bank
    prep_fold<<<1, 64>>>(Wp1, p_g, p_b, p_m, p_v, Wp2, bp2,
                         w1_g, w1_b, w1_m, w1_v, Ww1,
                         w2_g, w2_b, w2_m, w2_v, Ww2, bw2);
    void* src = nullptr;
    cudaGetSymbolAddress(&src, cFoldBuf);
    cudaMemcpyToSymbolAsync(cF, src, 396 * sizeof(float), 0,
                            cudaMemcpyDeviceToDevice, 0);

    const int smem_bytes = SMEM_FLOATS * (int)sizeof(float);  // ~84.6 KB
    cudaFuncSetAttribute(pt_fused_kernel,
                         cudaFuncAttributeMaxDynamicSharedMemorySize, smem_bytes);

    const int nblocks = 4 * NTILES;   // 592 = 2 exact waves at 2 blocks/SM
    pt_fused_kernel<<<nblocks, 256, smem_bytes>>>(
        points, feats, Wq, bq, Wk, bk, Wv, bv, out);
}

// round 16
// speedup vs baseline: 2.4351x; 1.0020x over previous
#include <cuda_runtime.h>

#define NPTS   16384
#define RAD    8
#define QPITCH 100
#define OPITCH 68
#define SPITCH 49
#define EPSC   1e-5f
#define L2E    1.44269504088896340736f

#define NTILES 148           // tiles per batch == SM count
#define TBASE  110           // 104 tiles of 111 + 44 tiles of 110 = 16384
#define TREM   104
#define HALMAX 127           // 111 + 2*RAD

// smem: scratch 8192 (feat/e-quads/S-exchange/staging), qkv 12700, pts 256
#define SMEM_FLOATS (8192 + HALMAX*QPITCH + 256)

__device__   __align__(16) float cFoldBuf[396];
__constant__ __align__(16) float cF[396];

#define PACK2(dst, lo, hi) asm("mov.b64 %0, {%1, %2};" : "=l"(dst) : "f"(lo), "f"(hi))
#define UNPACK2(lo, hi, v) asm("mov.b64 {%0, %1}, %2;" : "=f"(lo), "=f"(hi) : "l"(v))
#define FMA2(d, a, b, c)   asm("fma.rn.f32x2 %0, %1, %2, %3;" : "=l"(d) : "l"(a), "l"(b), "l"(c))
#define ADD2(d, a, b)      asm("add.rn.f32x2 %0, %1, %2;" : "=l"(d) : "l"(a), "l"(b))

__global__ void prep_fold(const float* __restrict__ Wp1,
                          const float* __restrict__ p_g, const float* __restrict__ p_b,
                          const float* __restrict__ p_m, const float* __restrict__ p_v,
                          const float* __restrict__ Wp2, const float* __restrict__ bp2,
                          const float* __restrict__ w1_g, const float* __restrict__ w1_b,
                          const float* __restrict__ w1_m, const float* __restrict__ w1_v,
                          const float* __restrict__ Ww1,
                          const float* __restrict__ w2_g, const float* __restrict__ w2_b,
                          const float* __restrict__ w2_m, const float* __restrict__ w2_v,
                          const float* __restrict__ Ww2,  const float* __restrict__ bw2)
{
    const int tid = threadIdx.x;
    float* buf = cFoldBuf;
    if (tid < 64)
        ((float4*)(buf + 128))[tid] = make_float4(Wp2[tid], Wp2[64 + tid], bp2[tid], 0.f);
    if (tid < 16) {
        float As  = Wp2[tid]    + Wp2[16+tid] + Wp2[32+tid] + Wp2[48+tid];
        float Bs  = Wp2[64+tid] + Wp2[80+tid] + Wp2[96+tid] + Wp2[112+tid];
        float bps = bp2[tid] + bp2[16+tid] + bp2[32+tid] + bp2[48+tid];
        float s   = w1_g[tid] * rsqrtf(w1_v[tid] + EPSC);
        float w1beff = w1_b[tid] - w1_m[tid]*s;
        ((float2*)buf)[tid]        = make_float2(As*s, Bs*s);
        ((float2*)(buf + 32))[tid] = make_float2(Ww1[2*tid], Ww1[2*tid+1]);
        buf[64 + tid] = bps*s + w1beff;
        buf[80 + tid] = s;
    }
    if (tid < 8)
        ((float4*)(buf + 96))[tid] = make_float4(Ww2[tid]*L2E, Ww2[8+tid]*L2E, bw2[tid]*L2E, 0.f);
    if (tid < 2) {
        float s = p_g[tid] * rsqrtf(p_v[tid] + EPSC);
        buf[384+4+tid] = s; buf[384+6+tid] = p_b[tid] - p_m[tid]*s;
        float s2 = w2_g[tid] * rsqrtf(w2_v[tid] + EPSC);
        buf[384+8+tid] = s2; buf[384+10+tid] = w2_b[tid] - w2_m[tid]*s2;
    }
    if (tid < 4) buf[384 + tid] = Wp1[tid];
}

__global__ __launch_bounds__(256, 2)
void pt_fused_kernel(const float* __restrict__ points,
                     const float* __restrict__ features,
                     const float* __restrict__ Wq,  const float* __restrict__ bq,
                     const float* __restrict__ Wk,  const float* __restrict__ bk,
                     const float* __restrict__ Wv,  const float* __restrict__ bv,
                     float* __restrict__ out)
{
    extern __shared__ float sm[];
    float* scratch = sm;                        // 8192: feat -> e-quads -> S -> staging
    float* qkv_sh  = scratch + 8192;            // 12700
    float* pts_sh  = qkv_sh  + HALMAX*QPITCH;   // 256

    const float2* cM2  = (const float2*)cF;
    const float2* cW2  = (const float2*)(cF + 32);
    const float*  cP0  = cF + 64;
    const float*  cS   = cF + 80;
    const float4* cE4  = (const float4*)(cF + 96);
    const float4* cR4  = (const float4*)(cF + 128);
    const float*  misc = cF + 384;

    const int tid    = threadIdx.x;
    const int bidx   = blockIdx.x;
    const int batch  = bidx / NTILES;
    const int ti     = bidx - batch * NTILES;
    const int tsz    = (ti < TREM) ? (TBASE + 1) : TBASE;
    const int tstart = ti * TBASE + ((ti < TREM) ? ti : TREM);
    const int hal    = tsz + 2*RAD;             // 126 or 127

    // ---- stage halo features + coords ----
    {
        const float4* fglob = (const float4*)features;
        for (int i = tid; i < hal*16; i += 256) {
            int h = i >> 4, k4 = i & 15;
            int row = batch*NPTS + ((tstart + h - RAD) & (NPTS - 1));
            ((float4*)scratch)[h*16 + k4] = fglob[row*16 + k4];
        }
        const float2* pglob = (const float2*)points;
        for (int i = tid; i < hal; i += 256) {
            int row = batch*NPTS + ((tstart + i - RAD) & (NPTS - 1));
            ((float2*)pts_sh)[i] = pglob[row];
        }
    }

    // ---- phase-1 weight preload: one channel column per lane, packed f32x2 ----
    const int warp = tid >> 5, lane = tid & 31;
    int cg, sub, npw;
    if (warp < 3)      { cg = 0; sub = warp;     npw = 3; }
    else if (warp < 6) { cg = 1; sub = warp - 3; npw = 3; }
    else               { cg = 2; sub = warp - 6; npw = 2; }
    const int c = cg*32 + lane;

    unsigned long long wp[32];
    float bias;
    if (c < 16) {
        bias = bq[c];
        #pragma unroll
        for (int i = 0; i < 32; ++i) PACK2(wp[i], Wq[(2*i)*16 + c], Wq[(2*i+1)*16 + c]);
    } else if (c < 32) {
        int cc = c - 16; bias = bk[cc];
        #pragma unroll
        for (int i = 0; i < 32; ++i) PACK2(wp[i], Wk[(2*i)*16 + cc], Wk[(2*i+1)*16 + cc]);
    } else {
        int cc = c - 32; bias = bv[cc];
        #pragma unroll
        for (int i = 0; i < 32; ++i) PACK2(wp[i], Wv[(2*i)*64 + cc], Wv[(2*i+1)*64 + cc]);
    }
    __syncthreads();

    const float chan_scale = (c < 32) ? cS[c & 15] : 1.0f;
    const float sbias = bias * chan_scale;

    // ---- phase 1: q/k/v GEMM over hal rows -> qkv_sh[p*QPITCH + c] ----
    {
        const int pbeg = (sub * hal) / npw;
        const int pend = ((sub + 1) * hal) / npw;
        #pragma unroll 2
        for (int p = pbeg; p < pend; ++p) {
            const ulonglong2* fr = (const ulonglong2*)(scratch + (p << 6));
            unsigned long long aA = 0ull, aB = 0ull, aC = 0ull, aD = 0ull;
            #pragma unroll
            for (int k2 = 0; k2 < 8; ++k2) {
                ulonglong2 f0 = fr[2*k2];
                ulonglong2 f1 = fr[2*k2 + 1];
                FMA2(aA, f0.x, wp[4*k2    ], aA);
                FMA2(aB, f0.y, wp[4*k2 + 1], aB);
                FMA2(aC, f1.x, wp[4*k2 + 2], aC);
                FMA2(aD, f1.y, wp[4*k2 + 3], aD);
            }
            unsigned long long u, v2r;
            ADD2(u, aA, aB); ADD2(v2r, aC, aD); ADD2(u, u, v2r);
            float lo, hi; UNPACK2(lo, hi, u);
            qkv_sh[p*QPITCH + c] = fmaf(lo + hi, chan_scale, sbias);
        }
    }
    __syncthreads();

    // ---- phase 2 (threads with p_raw >= tsz clamp and duplicate point tsz-1) ----
    const int p_raw = tid & 127;
    const int half  = tid >> 7;
    const int p     = (p_raw < tsz) ? p_raw : (tsz - 1);
    const int hme   = p + RAD;

    unsigned long long vacc2[16];
    #pragma unroll
    for (int i = 0; i < 16; ++i) vacc2[i] = 0ull;
    float S0[8], S1[8], SE[8];
    #pragma unroll
    for (int i = 0; i < 8; ++i) { S0[i] = 0.f; S1[i] = 0.f; SE[i] = 0.f; }

    const float W00 = misc[0], W01 = misc[1], W10 = misc[2], W11 = misc[3];
    const float ps0 = misc[4], ps1 = misc[5], pb0 = misc[6], pb1 = misc[7];
    const float w2s0 = misc[8], w2s1 = misc[9], w2b0 = misc[10], w2b1 = misc[11];

    #pragma unroll 1
    for (int chunk = 0; chunk < 2; ++chunk) {
        // ---- 2a: MLP+softmax once per (p, j); this thread: j = chunk*8 + 2k + half
        {
            const float2 pme = ((const float2*)pts_sh)[hme];
            float P[16];
            {
                const float4* q4 = (const float4*)(qkv_sh + hme*QPITCH);
                #pragma unroll
                for (int m4 = 0; m4 < 4; ++m4) {
                    float4 t = q4[m4];
                    P[4*m4  ] = cP0[4*m4  ] - t.x;
                    P[4*m4+1] = cP0[4*m4+1] - t.y;
                    P[4*m4+2] = cP0[4*m4+2] - t.z;
                    P[4*m4+3] = cP0[4*m4+3] - t.w;
                }
            }
            #pragma unroll 2
            for (int k = 0; k < 4; ++k) {
                const int jj  = chunk*8 + 2*k + half;
                const int off = jj - 8 + (jj >> 3);
                const int h   = hme + off;

                const float2 pn = ((const float2*)pts_sh)[h];
                const float dx = pn.x - pme.x;
                const float dy = pn.y - pme.y;
                const float h0 = fmaxf(fmaf(dx*W00 + dy*W10, ps0, pb0), 0.f);
                const float h1 = fmaxf(fmaf(dx*W01 + dy*W11, ps1, pb1), 0.f);

                float t0a = 0.f, t0b = 0.f, t1a = 0.f, t1b = 0.f;
                const float4* k4p = (const float4*)(qkv_sh + h*QPITCH + 16);
                const float4* m4p = (const float4*)cM2;
                const float4* w4p = (const float4*)cW2;
                #pragma unroll
                for (int m4 = 0; m4 < 4; ++m4) {
                    float4 kk = k4p[m4];
                    float4 ma = m4p[2*m4], mb = m4p[2*m4+1];
                    float4 wa = w4p[2*m4], wb = w4p[2*m4+1];
                    int m0 = 4*m4;
                    float wr0 = fmaxf(fmaf(h0, ma.x, fmaf(h1, ma.y, kk.x + P[m0  ])), 0.f);
                    float wr1 = fmaxf(fmaf(h0, ma.z, fmaf(h1, ma.w, kk.y + P[m0+1])), 0.f);
                    float wr2 = fmaxf(fmaf(h0, mb.x, fmaf(h1, mb.y, kk.z + P[m0+2])), 0.f);
                    float wr3 = fmaxf(fmaf(h0, mb.z, fmaf(h1, mb.w, kk.w + P[m0+3])), 0.f);
                    t0a = fmaf(wr0, wa.x, t0a);  t1a = fmaf(wr0, wa.y, t1a);
                    t0b = fmaf(wr1, wa.z, t0b);  t1b = fmaf(wr1, wa.w, t1b);
                    t0a = fmaf(wr2, wb.x, t0a);  t1a = fmaf(wr2, wb.y, t1a);
                    t0b = fmaf(wr3, wb.z, t0b);  t1b = fmaf(wr3, wb.w, t1b);
                }
                float t0 = t0a + t0b, t1 = t1a + t1b;
                t0 = fmaxf(fmaf(t0, w2s0, w2b0), 0.f);
                t1 = fmaxf(fmaf(t1, w2s1, w2b1), 0.f);

                // softmax in log2 domain; logits bounded -> no max-shift needed
                float e[8];
                #pragma unroll
                for (int cc = 0; cc < 8; ++cc) {
                    float4 ce = cE4[cc];
                    e[cc] = exp2f(fmaf(t0, ce.x, fmaf(t1, ce.y, ce.z)));
                }
                float sA = (e[0]+e[1]) + (e[2]+e[3]);
                float sB = (e[4]+e[5]) + (e[6]+e[7]);
                const float inv = __fdividef(1.0f, sA + sB);
                #pragma unroll
                for (int cc = 0; cc < 8; ++cc) e[cc] *= inv;

                #pragma unroll
                for (int cc = 0; cc < 8; ++cc) {
                    S0[cc] = fmaf(h0, e[cc], S0[cc]);
                    S1[cc] = fmaf(h1, e[cc], S1[cc]);
                    SE[cc] += e[cc];
                }
                // store e as two quads: float4 scratch4[plane*1024 + jr*128 + p]
                {
                    float4* eq = (float4*)scratch;
                    eq[(jj & 7)*128 + p]        = make_float4(e[0], e[1], e[2], e[3]);
                    eq[1024 + (jj & 7)*128 + p] = make_float4(e[4], e[5], e[6], e[7]);
                }
            }
        }
        __syncthreads();

        // ---- 2b: packed f32x2 weighted-v accumulation (32 channels/thread) ----
        #pragma unroll 2
        for (int jr = 0; jr < 8; ++jr) {
            const int jj  = chunk*8 + jr;
            const int off = jj - 8 + (jj >> 3);
            const int h   = hme + off;
            const ulonglong2* eq = (const ulonglong2*)scratch;
            ulonglong2 ea = eq[jr*128 + p];
            ulonglong2 eb = eq[1024 + jr*128 + p];
            unsigned long long e2[4];
            e2[0] = ea.x; e2[1] = ea.y; e2[2] = eb.x; e2[3] = eb.y;
            const ulonglong2* v2 = (const ulonglong2*)(qkv_sh + h*QPITCH + 32 + half*32);
            #pragma unroll
            for (int i = 0; i < 8; ++i) {
                ulonglong2 v = v2[i];
                FMA2(vacc2[2*i  ], v.x, e2[(2*i  ) & 3], vacc2[2*i  ]);
                FMA2(vacc2[2*i+1], v.y, e2[(2*i+1) & 3], vacc2[2*i+1]);
            }
        }
        __syncthreads();
    }

    // ---- unpack accumulators ----
    float va[32];
    #pragma unroll
    for (int t = 0; t < 16; ++t) UNPACK2(va[2*t], va[2*t+1], vacc2[t]);

    // ---- combine S partials across the two j-parity threads of this point ----
    {
        float* sp = scratch + p*SPITCH + half*24;
        #pragma unroll
        for (int i = 0; i < 8; ++i) { sp[i] = S0[i]; sp[8+i] = S1[i]; sp[16+i] = SE[i]; }
    }
    __syncthreads();
    {
        const float* so = scratch + p*SPITCH + (half^1)*24;
        #pragma unroll
        for (int i = 0; i < 8; ++i) { S0[i] += so[i]; S1[i] += so[8+i]; SE[i] += so[16+i]; }
    }
    // apply factored positional term
    #pragma unroll
    for (int c4 = 0; c4 < 8; ++c4) {
        int cb = half*32 + 4*c4;
        float4 r0 = cR4[cb], r1 = cR4[cb+1], r2 = cR4[cb+2], r3 = cR4[cb+3];
        va[c4*4  ] += fmaf(r0.x, S0[(c4*4  )&7], fmaf(r0.y, S1[(c4*4  )&7], r0.z*SE[(c4*4  )&7]));
        va[c4*4+1] += fmaf(r1.x, S0[(c4*4+1)&7], fmaf(r1.y, S1[(c4*4+1)&7], r1.z*SE[(c4*4+1)&7]));
        va[c4*4+2] += fmaf(r2.x, S0[(c4*4+2)&7], fmaf(r2.y, S1[(c4*4+2)&7], r2.z*SE[(c4*4+2)&7]));
        va[c4*4+3] += fmaf(r3.x, S0[(c4*4+3)&7], fmaf(r3.y, S1[(c4*4+3)&7], r3.z*SE[(c4*4+3)&7]));
    }
    __syncthreads();   // S-exchange reads done before staging overwrite

    // ---- stage (pitch 68) and coalesced write-out ----
    {
        float4* st = (float4*)(scratch + p*OPITCH + half*32);
        #pragma unroll
        for (int c4 = 0; c4 < 8; ++c4)
            st[c4] = make_float4(va[c4*4], va[c4*4+1], va[c4*4+2], va[c4*4+3]);
    }
    __syncthreads();
    {
        float4* dst = (float4*)(out + (size_t)(batch*NPTS + tstart) * 64);
        for (int i = tid; i < tsz*16; i += 256) {
            int pp = i >> 4, k4 = i & 15;
            dst[i] = ((const float4*)(scratch + pp*OPITCH))[k4];
        }
    }
}

extern "C" void kernel_launch(void* const* d_in, const int* in_sizes, int n_in,
                              void* d_out, int out_size)
{
    const float* points = (const float*)d_in[0];
    const float* feats  = (const float*)d_in[1];
    const float* Wq   = (const float*)d_in[2];
    const float* bq   = (const float*)d_in[3];
    const float* Wk   = (const float*)d_in[4];
    const float* bk   = (const float*)d_in[5];
    const float* Wv   = (const float*)d_in[6];
    const float* bv   = (const float*)d_in[7];
    const float* Wp1  = (const float*)d_in[8];
    const float* p_g  = (const float*)d_in[9];
    const float* p_b  = (const float*)d_in[10];
    const float* p_m  = (const float*)d_in[11];
    const float* p_v  = (const float*)d_in[12];
    const float* Wp2  = (const float*)d_in[13];
    const float* bp2  = (const float*)d_in[14];
    const float* w1_g = (const float*)d_in[15];
    const float* w1_b = (const float*)d_in[16];
    const float* w1_m = (const float*)d_in[17];
    const float* w1_v = (const float*)d_in[18];
    const float* Ww1  = (const float*)d_in[19];
    const float* w2_g = (const float*)d_in[20];
    const float* w2_b = (const float*)d_in[21];
    const float* w2_m = (const float*)d_in[22];
    const float* w2_v = (const float*)d_in[23];
    const float* Ww2  = (const float*)d_in[24];
    const float* bw2  = (const float*)d_in[25];
    float* out = (float*)d_out;

    // fold constants -> __device__ buffer -> __constant__ bank
    prep_fold<<<1, 64>>>(Wp1, p_g, p_b, p_m, p_v, Wp2, bp2,
                         w1_g, w1_b, w1_m, w1_v, Ww1,
                         w2_g, w2_b, w2_m, w2_v, Ww2, bw2);
    void* src = nullptr;
    cudaGetSymbolAddress(&src, cFoldBuf);
    cudaMemcpyToSymbolAsync(cF, src, 396 * sizeof(float), 0,
                            cudaMemcpyDeviceToDevice, 0);

    const int smem_bytes = SMEM_FLOATS * (int)sizeof(float);  // ~84.6 KB
    cudaFuncSetAttribute(pt_fused_kernel,
                         cudaFuncAttributeMaxDynamicSharedMemorySize, smem_bytes);

    const int nblocks = 4 * NTILES;   // 592 = 2 exact waves at 2 blocks/SM
    pt_fused_kernel<<<nblocks, 256, smem_bytes>>>(
        points, feats, Wq, bq, Wk, bk, Wv, bv, out);
}

// round 17
// speedup vs baseline: 2.5085x; 1.0302x over previous
#include <cuda_runtime.h>
#include <cuda_fp16.h>

#define NPTS   16384
#define RAD    8
#define QP     68            // qkv pitch (words): 32 fp32 q/k + 64 fp16 v (128B) + pad
#define OPITCH 68
#define SPITCH 49
#define EPSC   1e-5f
#define L2E    1.44269504088896340736f

#define NTILES 148
#define TBASE  110           // 104 tiles of 111 + 44 tiles of 110 = 16384
#define TREM   104
#define HALMAX 127           // 111 + 2*RAD

// smem: scratch 8192 (feat/e-quads/S-exchange/staging), qkv 127*68=8636, pts 256
#define SMEM_FLOATS (8192 + HALMAX*QP + 256)

__device__   __align__(16) float cFoldBuf[396];
__constant__ __align__(16) float cF[396];

#define PACK2(dst, lo, hi) asm("mov.b64 %0, {%1, %2};" : "=l"(dst) : "f"(lo), "f"(hi))
#define UNPACK2(lo, hi, v) asm("mov.b64 {%0, %1}, %2;" : "=f"(lo), "=f"(hi) : "l"(v))
#define FMA2(d, a, b, c)   asm("fma.rn.f32x2 %0, %1, %2, %3;" : "=l"(d) : "l"(a), "l"(b), "l"(c))
#define ADD2(d, a, b)      asm("add.rn.f32x2 %0, %1, %2;" : "=l"(d) : "l"(a), "l"(b))

__global__ void prep_fold(const float* __restrict__ Wp1,
                          const float* __restrict__ p_g, const float* __restrict__ p_b,
                          const float* __restrict__ p_m, const float* __restrict__ p_v,
                          const float* __restrict__ Wp2, const float* __restrict__ bp2,
                          const float* __restrict__ w1_g, const float* __restrict__ w1_b,
                          const float* __restrict__ w1_m, const float* __restrict__ w1_v,
                          const float* __restrict__ Ww1,
                          const float* __restrict__ w2_g, const float* __restrict__ w2_b,
                          const float* __restrict__ w2_m, const float* __restrict__ w2_v,
                          const float* __restrict__ Ww2,  const float* __restrict__ bw2)
{
    const int tid = threadIdx.x;
    float* buf = cFoldBuf;
    if (tid < 64)
        ((float4*)(buf + 128))[tid] = make_float4(Wp2[tid], Wp2[64 + tid], bp2[tid], 0.f);
    if (tid < 16) {
        float As  = Wp2[tid]    + Wp2[16+tid] + Wp2[32+tid] + Wp2[48+tid];
        float Bs  = Wp2[64+tid] + Wp2[80+tid] + Wp2[96+tid] + Wp2[112+tid];
        float bps = bp2[tid] + bp2[16+tid] + bp2[32+tid] + bp2[48+tid];
        float s   = w1_g[tid] * rsqrtf(w1_v[tid] + EPSC);
        float w1beff = w1_b[tid] - w1_m[tid]*s;
        ((float2*)buf)[tid]        = make_float2(As*s, Bs*s);
        ((float2*)(buf + 32))[tid] = make_float2(Ww1[2*tid], Ww1[2*tid+1]);
        buf[64 + tid] = bps*s + w1beff;
        buf[80 + tid] = s;
    }
    if (tid < 8)
        ((float4*)(buf + 96))[tid] = make_float4(Ww2[tid]*L2E, Ww2[8+tid]*L2E, bw2[tid]*L2E, 0.f);
    if (tid < 2) {
        float s = p_g[tid] * rsqrtf(p_v[tid] + EPSC);
        buf[384+4+tid] = s; buf[384+6+tid] = p_b[tid] - p_m[tid]*s;
        float s2 = w2_g[tid] * rsqrtf(w2_v[tid] + EPSC);
        buf[384+8+tid] = s2; buf[384+10+tid] = w2_b[tid] - w2_m[tid]*s2;
    }
    if (tid < 4) buf[384 + tid] = Wp1[tid];
}

__global__ __launch_bounds__(256, 2)
void pt_fused_kernel(const float* __restrict__ points,
                     const float* __restrict__ features,
                     const float* __restrict__ Wq,  const float* __restrict__ bq,
                     const float* __restrict__ Wk,  const float* __restrict__ bk,
                     const float* __restrict__ Wv,  const float* __restrict__ bv,
                     float* __restrict__ out)
{
    extern __shared__ float sm[];
    float* scratch = sm;                        // 8192: feat -> e-quads -> S -> staging
    float* qkv_sh  = scratch + 8192;            // 8636 (rows: 32 f32 + 64 f16 + pad)
    float* pts_sh  = qkv_sh  + HALMAX*QP;       // 256

    const float2* cM2  = (const float2*)cF;
    const float2* cW2  = (const float2*)(cF + 32);
    const float*  cP0  = cF + 64;
    const float*  cS   = cF + 80;
    const float4* cE4  = (const float4*)(cF + 96);
    const float4* cR4  = (const float4*)(cF + 128);
    const float*  misc = cF + 384;

    const int tid    = threadIdx.x;
    const int bidx   = blockIdx.x;
    const int batch  = bidx / NTILES;
    const int ti     = bidx - batch * NTILES;
    const int tsz    = (ti < TREM) ? (TBASE + 1) : TBASE;
    const int tstart = ti * TBASE + ((ti < TREM) ? ti : TREM);
    const int hal    = tsz + 2*RAD;             // 126 or 127

    // ---- stage halo features + coords ----
    {
        const float4* fglob = (const float4*)features;
        for (int i = tid; i < hal*16; i += 256) {
            int h = i >> 4, k4 = i & 15;
            int row = batch*NPTS + ((tstart + h - RAD) & (NPTS - 1));
            ((float4*)scratch)[h*16 + k4] = fglob[row*16 + k4];
        }
        const float2* pglob = (const float2*)points;
        for (int i = tid; i < hal; i += 256) {
            int row = batch*NPTS + ((tstart + i - RAD) & (NPTS - 1));
            ((float2*)pts_sh)[i] = pglob[row];
        }
    }

    // ---- phase-1 weight preload: one channel column per lane, packed f32x2 ----
    const int warp = tid >> 5, lane = tid & 31;
    int cg, sub, npw;
    if (warp < 3)      { cg = 0; sub = warp;     npw = 3; }
    else if (warp < 6) { cg = 1; sub = warp - 3; npw = 3; }
    else               { cg = 2; sub = warp - 6; npw = 2; }
    const int c = cg*32 + lane;

    unsigned long long wp[32];
    float bias;
    if (c < 16) {
        bias = bq[c];
        #pragma unroll
        for (int i = 0; i < 32; ++i) PACK2(wp[i], Wq[(2*i)*16 + c], Wq[(2*i+1)*16 + c]);
    } else if (c < 32) {
        int cc = c - 16; bias = bk[cc];
        #pragma unroll
        for (int i = 0; i < 32; ++i) PACK2(wp[i], Wk[(2*i)*16 + cc], Wk[(2*i+1)*16 + cc]);
    } else {
        int cc = c - 32; bias = bv[cc];
        #pragma unroll
        for (int i = 0; i < 32; ++i) PACK2(wp[i], Wv[(2*i)*64 + cc], Wv[(2*i+1)*64 + cc]);
    }
    __syncthreads();

    const float chan_scale = (c < 32) ? cS[c & 15] : 1.0f;
    const float sbias = bias * chan_scale;

    // ---- phase 1: q/k/v GEMM over hal rows; q/k fp32, v stored fp16 ----
    {
        const int pbeg = (sub * hal) / npw;
        const int pend = ((sub + 1) * hal) / npw;
        #pragma unroll 2
        for (int p = pbeg; p < pend; ++p) {
            const ulonglong2* fr = (const ulonglong2*)(scratch + (p << 6));
            unsigned long long aA = 0ull, aB = 0ull, aC = 0ull, aD = 0ull;
            #pragma unroll
            for (int k2 = 0; k2 < 8; ++k2) {
                ulonglong2 f0 = fr[2*k2];
                ulonglong2 f1 = fr[2*k2 + 1];
                FMA2(aA, f0.x, wp[4*k2    ], aA);
                FMA2(aB, f0.y, wp[4*k2 + 1], aB);
                FMA2(aC, f1.x, wp[4*k2 + 2], aC);
                FMA2(aD, f1.y, wp[4*k2 + 3], aD);
            }
            unsigned long long u, v2r;
            ADD2(u, aA, aB); ADD2(v2r, aC, aD); ADD2(u, u, v2r);
            float lo, hi; UNPACK2(lo, hi, u);
            float val = fmaf(lo + hi, chan_scale, sbias);
            if (c < 32) {
                qkv_sh[p*QP + c] = val;
            } else {
                __half* vrow = (__half*)((char*)(qkv_sh + p*QP) + 128);
                vrow[c - 32] = __float2half(val);
            }
        }
    }
    __syncthreads();

    // ---- phase 2 (threads with p_raw >= tsz clamp and duplicate point tsz-1) ----
    const int p_raw = tid & 127;
    const int half  = tid >> 7;
    const int p     = (p_raw < tsz) ? p_raw : (tsz - 1);
    const int hme   = p + RAD;

    unsigned long long vacc2[16];
    #pragma unroll
    for (int i = 0; i < 16; ++i) vacc2[i] = 0ull;
    float S0[8], S1[8], SE[8];
    #pragma unroll
    for (int i = 0; i < 8; ++i) { S0[i] = 0.f; S1[i] = 0.f; SE[i] = 0.f; }

    const float W00 = misc[0], W01 = misc[1], W10 = misc[2], W11 = misc[3];
    const float ps0 = misc[4], ps1 = misc[5], pb0 = misc[6], pb1 = misc[7];
    const float w2s0 = misc[8], w2s1 = misc[9], w2b0 = misc[10], w2b1 = misc[11];

    #pragma unroll 1
    for (int chunk = 0; chunk < 2; ++chunk) {
        // ---- 2a: MLP+softmax once per (p, j); this thread: j = chunk*8 + 2k + half
        {
            const float2 pme = ((const float2*)pts_sh)[hme];
            float P[16];
            {
                const float4* q4 = (const float4*)(qkv_sh + hme*QP);
                #pragma unroll
                for (int m4 = 0; m4 < 4; ++m4) {
                    float4 t = q4[m4];
                    P[4*m4  ] = cP0[4*m4  ] - t.x;
                    P[4*m4+1] = cP0[4*m4+1] - t.y;
                    P[4*m4+2] = cP0[4*m4+2] - t.z;
                    P[4*m4+3] = cP0[4*m4+3] - t.w;
                }
            }
            #pragma unroll 2
            for (int k = 0; k < 4; ++k) {
                const int jj  = chunk*8 + 2*k + half;
                const int off = jj - 8 + (jj >> 3);
                const int h   = hme + off;

                const float2 pn = ((const float2*)pts_sh)[h];
                const float dx = pn.x - pme.x;
                const float dy = pn.y - pme.y;
                const float h0 = fmaxf(fmaf(dx*W00 + dy*W10, ps0, pb0), 0.f);
                const float h1 = fmaxf(fmaf(dx*W01 + dy*W11, ps1, pb1), 0.f);

                float t0a = 0.f, t0b = 0.f, t1a = 0.f, t1b = 0.f;
                const float4* k4p = (const float4*)(qkv_sh + h*QP + 16);
                const float4* m4p = (const float4*)cM2;
                const float4* w4p = (const float4*)cW2;
                #pragma unroll
                for (int m4 = 0; m4 < 4; ++m4) {
                    float4 kk = k4p[m4];
                    float4 ma = m4p[2*m4], mb = m4p[2*m4+1];
                    float4 wa = w4p[2*m4], wb = w4p[2*m4+1];
                    int m0 = 4*m4;
                    float wr0 = fmaxf(fmaf(h0, ma.x, fmaf(h1, ma.y, kk.x + P[m0  ])), 0.f);
                    float wr1 = fmaxf(fmaf(h0, ma.z, fmaf(h1, ma.w, kk.y + P[m0+1])), 0.f);
                    float wr2 = fmaxf(fmaf(h0, mb.x, fmaf(h1, mb.y, kk.z + P[m0+2])), 0.f);
                    float wr3 = fmaxf(fmaf(h0, mb.z, fmaf(h1, mb.w, kk.w + P[m0+3])), 0.f);
                    t0a = fmaf(wr0, wa.x, t0a);  t1a = fmaf(wr0, wa.y, t1a);
                    t0b = fmaf(wr1, wa.z, t0b);  t1b = fmaf(wr1, wa.w, t1b);
                    t0a = fmaf(wr2, wb.x, t0a);  t1a = fmaf(wr2, wb.y, t1a);
                    t0b = fmaf(wr3, wb.z, t0b);  t1b = fmaf(wr3, wb.w, t1b);
                }
                float t0 = t0a + t0b, t1 = t1a + t1b;
                t0 = fmaxf(fmaf(t0, w2s0, w2b0), 0.f);
                t1 = fmaxf(fmaf(t1, w2s1, w2b1), 0.f);

                // softmax in log2 domain; logits bounded -> no max-shift needed
                float e[8];
                #pragma unroll
                for (int cc = 0; cc < 8; ++cc) {
                    float4 ce = cE4[cc];
                    e[cc] = exp2f(fmaf(t0, ce.x, fmaf(t1, ce.y, ce.z)));
                }
                float sA = (e[0]+e[1]) + (e[2]+e[3]);
                float sB = (e[4]+e[5]) + (e[6]+e[7]);
                const float inv = __fdividef(1.0f, sA + sB);
                #pragma unroll
                for (int cc = 0; cc < 8; ++cc) e[cc] *= inv;

                #pragma unroll
                for (int cc = 0; cc < 8; ++cc) {
                    S0[cc] = fmaf(h0, e[cc], S0[cc]);
                    S1[cc] = fmaf(h1, e[cc], S1[cc]);
                    SE[cc] += e[cc];
                }
                // store e as two quads: float4 scratch4[plane*1024 + jr*128 + p]
                {
                    float4* eq = (float4*)scratch;
                    eq[(jj & 7)*128 + p]        = make_float4(e[0], e[1], e[2], e[3]);
                    eq[1024 + (jj & 7)*128 + p] = make_float4(e[4], e[5], e[6], e[7]);
                }
            }
        }
        __syncthreads();

        // ---- 2b: fp16 v load + f32x2 weighted accumulation (32 channels/thread) ----
        #pragma unroll 2
        for (int jr = 0; jr < 8; ++jr) {
            const int jj  = chunk*8 + jr;
            const int off = jj - 8 + (jj >> 3);
            const int h   = hme + off;
            const ulonglong2* eqp = (const ulonglong2*)scratch;
            ulonglong2 ea = eqp[jr*128 + p];
            ulonglong2 eb = eqp[1024 + jr*128 + p];
            unsigned long long e2[4];
            e2[0] = ea.x; e2[1] = ea.y; e2[2] = eb.x; e2[3] = eb.y;
            const uint4* v4 = (const uint4*)((const char*)(qkv_sh + h*QP) + 128 + half*64);
            #pragma unroll
            for (int i = 0; i < 4; ++i) {
                uint4 vv = v4[i];
                float2 f0 = __half22float2(*(__half2*)&vv.x);
                float2 f1 = __half22float2(*(__half2*)&vv.y);
                float2 f2 = __half22float2(*(__half2*)&vv.z);
                float2 f3 = __half22float2(*(__half2*)&vv.w);
                unsigned long long u0, u1, u2, u3;
                PACK2(u0, f0.x, f0.y); PACK2(u1, f1.x, f1.y);
                PACK2(u2, f2.x, f2.y); PACK2(u3, f3.x, f3.y);
                FMA2(vacc2[4*i  ], u0, e2[0], vacc2[4*i  ]);
                FMA2(vacc2[4*i+1], u1, e2[1], vacc2[4*i+1]);
                FMA2(vacc2[4*i+2], u2, e2[2], vacc2[4*i+2]);
                FMA2(vacc2[4*i+3], u3, e2[3], vacc2[4*i+3]);
            }
        }
        __syncthreads();
    }

    // ---- unpack accumulators ----
    float va[32];
    #pragma unroll
    for (int t = 0; t < 16; ++t) UNPACK2(va[2*t], va[2*t+1], vacc2[t]);

    // ---- combine S partials across the two j-parity threads of this point ----
    {
        float* sp = scratch + p*SPITCH + half*24;
        #pragma unroll
        for (int i = 0; i < 8; ++i) { sp[i] = S0[i]; sp[8+i] = S1[i]; sp[16+i] = SE[i]; }
    }
    __syncthreads();
    {
        const float* so = scratch + p*SPITCH + (half^1)*24;
        #pragma unroll
        for (int i = 0; i < 8; ++i) { S0[i] += so[i]; S1[i] += so[8+i]; SE[i] += so[16+i]; }
    }
    // apply factored positional term
    #pragma unroll
    for (int c4 = 0; c4 < 8; ++c4) {
        int cb = half*32 + 4*c4;
        float4 r0 = cR4[cb], r1 = cR4[cb+1], r2 = cR4[cb+2], r3 = cR4[cb+3];
        va[c4*4  ] += fmaf(r0.x, S0[(c4*4  )&7], fmaf(r0.y, S1[(c4*4  )&7], r0.z*SE[(c4*4  )&7]));
        va[c4*4+1] += fmaf(r1.x, S0[(c4*4+1)&7], fmaf(r1.y, S1[(c4*4+1)&7], r1.z*SE[(c4*4+1)&7]));
        va[c4*4+2] += fmaf(r2.x, S0[(c4*4+2)&7], fmaf(r2.y, S1[(c4*4+2)&7], r2.z*SE[(c4*4+2)&7]));
        va[c4*4+3] += fmaf(r3.x, S0[(c4*4+3)&7], fmaf(r3.y, S1[(c4*4+3)&7], r3.z*SE[(c4*4+3)&7]));
    }
    __syncthreads();   // S-exchange reads done before staging overwrite

    // ---- stage (pitch 68) and coalesced write-out ----
    {
        float4* st = (float4*)(scratch + p*OPITCH + half*32);
        #pragma unroll
        for (int c4 = 0; c4 < 8; ++c4)
            st[c4] = make_float4(va[c4*4], va[c4*4+1], va[c4*4+2], va[c4*4+3]);
    }
    __syncthreads();
    {
        float4* dst = (float4*)(out + (size_t)(batch*NPTS + tstart) * 64);
        for (int i = tid; i < tsz*16; i += 256) {
            int pp = i >> 4, k4 = i & 15;
            dst[i] = ((const float4*)(scratch + pp*OPITCH))[k4];
        }
    }
}

extern "C" void kernel_launch(void* const* d_in, const int* in_sizes, int n_in,
                              void* d_out, int out_size)
{
    const float* points = (const float*)d_in[0];
    const float* feats  = (const float*)d_in[1];
    const float* Wq   = (const float*)d_in[2];
    const float* bq   = (const float*)d_in[3];
    const float* Wk   = (const float*)d_in[4];
    const float* bk   = (const float*)d_in[5];
    const float* Wv   = (const float*)d_in[6];
    const float* bv   = (const float*)d_in[7];
    const float* Wp1  = (const float*)d_in[8];
    const float* p_g  = (const float*)d_in[9];
    const float* p_b  = (const float*)d_in[10];
    const float* p_m  = (const float*)d_in[11];
    const float* p_v  = (const float*)d_in[12];
    const float* Wp2  = (const float*)d_in[13];
    const float* bp2  = (const float*)d_in[14];
    const float* w1_g = (const float*)d_in[15];
    const float* w1_b = (const float*)d_in[16];
    const float* w1_m = (const float*)d_in[17];
    const float* w1_v = (const float*)d_in[18];
    const float* Ww1  = (const float*)d_in[19];
    const float* w2_g = (const float*)d_in[20];
    const float* w2_b = (const float*)d_in[21];
    const float* w2_m = (const float*)d_in[22];
    const float* w2_v = (const float*)d_in[23];
    const float* Ww2  = (const float*)d_in[24];
    const float* bw2  = (const float*)d_in[25];
    float* out = (float*)d_out;

    // fold constants -> __device__ buffer -> __constant__ bank
    prep_fold<<<1, 64>>>(Wp1, p_g, p_b, p_m, p_v, Wp2, bp2,
                         w1_g, w1_b, w1_m, w1_v, Ww1,
                         w2_g, w2_b, w2_m, w2_v, Ww2, bw2);
    void* src = nullptr;
    cudaGetSymbolAddress(&src, cFoldBuf);
    cudaMemcpyToSymbolAsync(cF, src, 396 * sizeof(float), 0,
                            cudaMemcpyDeviceToDevice, 0);

    const int smem_bytes = SMEM_FLOATS * (int)sizeof(float);  // ~68.3 KB
    cudaFuncSetAttribute(pt_fused_kernel,
                         cudaFuncAttributeMaxDynamicSharedMemorySize, smem_bytes);

    const int nblocks = 4 * NTILES;   // 592 = 2 exact waves at 2 blocks/SM
    pt_fused_kernel<<<nblocks, 256, smem_bytes>>>(
        points, feats, Wq, bq, Wk, bk, Wv, bv, out);
}